// round 5
// baseline (speedup 1.0000x reference)
#include <cuda_runtime.h>
#include <cuda_bf16.h>
#include <cstdint>
#include <math.h>

#define BATCH 2
#define SEQ   2048
#define DIM   4096
#define NH    32
#define NKV   8
#define HD    128
#define NREP  4
#define MTOT  (BATCH*SEQ)   // 4096
#define NQ    (NH*HD)       // 4096
#define NKVD  (NKV*HD)      // 1024

// -------- scratch (device globals) --------
__device__ float g_q[(size_t)MTOT*NQ];
__device__ float g_k[(size_t)MTOT*NKVD];
__device__ float g_v[(size_t)MTOT*NKVD];

__device__ __nv_bfloat16 g_xh[(size_t)MTOT*DIM],  g_xl[(size_t)MTOT*DIM];
__device__ __nv_bfloat16 g_wqTh[(size_t)NQ*DIM],  g_wqTl[(size_t)NQ*DIM];
__device__ __nv_bfloat16 g_wkTh[(size_t)NKVD*DIM],g_wkTl[(size_t)NKVD*DIM];
__device__ __nv_bfloat16 g_wvTh[(size_t)NKVD*DIM],g_wvTl[(size_t)NKVD*DIM];
__device__ __nv_bfloat16 g_woTh[(size_t)DIM*NQ],  g_woTl[(size_t)DIM*NQ];
__device__ __nv_bfloat16 g_aoh[(size_t)MTOT*NQ],  g_aol[(size_t)MTOT*NQ];
__device__ __nv_bfloat16 g_qh[(size_t)MTOT*NQ],   g_ql[(size_t)MTOT*NQ];
__device__ __nv_bfloat16 g_kh[(size_t)MTOT*NKVD], g_kl[(size_t)MTOT*NKVD];
__device__ __nv_bfloat16 g_vh[(size_t)MTOT*NKVD], g_vl[(size_t)MTOT*NKVD];

// ============================================================
// PTX helpers
// ============================================================
__device__ __forceinline__ uint32_t smem_u32(const void* p) {
    uint32_t a;
    asm("{ .reg .u64 t; cvta.to.shared.u64 t, %1; cvt.u32.u64 %0, t; }" : "=r"(a) : "l"(p));
    return a;
}
__device__ __forceinline__ void cp16(uint32_t dst, const void* src) {
    asm volatile("cp.async.cg.shared.global [%0], [%1], 16;" :: "r"(dst), "l"(src));
}
#define CP_COMMIT()  asm volatile("cp.async.commit_group;")
#define CP_WAIT1()   asm volatile("cp.async.wait_group 1;")

__device__ __forceinline__ void ldsm4(uint32_t* r, uint32_t addr) {
    asm volatile("ldmatrix.sync.aligned.m8n8.x4.shared.b16 {%0,%1,%2,%3}, [%4];"
        : "=r"(r[0]), "=r"(r[1]), "=r"(r[2]), "=r"(r[3]) : "r"(addr));
}
__device__ __forceinline__ void ldsm4t(uint32_t* r, uint32_t addr) {
    asm volatile("ldmatrix.sync.aligned.m8n8.x4.trans.shared.b16 {%0,%1,%2,%3}, [%4];"
        : "=r"(r[0]), "=r"(r[1]), "=r"(r[2]), "=r"(r[3]) : "r"(addr));
}
__device__ __forceinline__ void mma16816(float* c, const uint32_t* a, const uint32_t* b) {
    asm volatile("mma.sync.aligned.m16n8k16.row.col.f32.bf16.bf16.f32 "
        "{%0,%1,%2,%3}, {%4,%5,%6,%7}, {%8,%9}, {%0,%1,%2,%3};"
        : "+f"(c[0]), "+f"(c[1]), "+f"(c[2]), "+f"(c[3])
        : "r"(a[0]), "r"(a[1]), "r"(a[2]), "r"(a[3]), "r"(b[0]), "r"(b[1]));
}
__device__ __forceinline__ uint32_t packbf(float a, float b) {
    __nv_bfloat162 v = __floats2bfloat162_rn(a, b);
    return *(uint32_t*)&v;
}

// swizzled byte offset inside a [rows x 32bf16] tile (64B rows, 4 segs)
__device__ __forceinline__ uint32_t swz(int row, int seg) {
    return (uint32_t)row * 64u + ((uint32_t)(seg ^ ((row >> 1) & 3)) << 4);
}

// ============================================================
// split-bf16 GEMM v2: CTA 128(M) x 256(N), BK=32, 8 warps (2x4),
// warp tile 64x64, 3-stage cp.async, all ldsm4.
// C[M,N] = (Ah+Al)[M,K] @ (Bh+Bl)[N,K]^T
// ============================================================
#define BM 128
#define BN 256
#define BK 32
#define GOFF_AH 0u
#define GOFF_AL 8192u
#define GOFF_BH 16384u
#define GOFF_BL 32768u
#define GSTAGE  49152u
#define GEMM_SMEM (3*49152)

__global__ void __launch_bounds__(256, 1) gemm_mma256(
    const __nv_bfloat16* __restrict__ Ah, const __nv_bfloat16* __restrict__ Al,
    const __nv_bfloat16* __restrict__ Bh, const __nv_bfloat16* __restrict__ Bl,
    float* __restrict__ C, int M, int N, int K)
{
    extern __shared__ char smem[];
    const uint32_t sb = smem_u32(smem);
    const int t = threadIdx.x;
    const int lane = t & 31, wid = t >> 5;
    const int m0 = blockIdx.y * BM, n0 = blockIdx.x * BN;

    // ---- loader mapping ----
    // A: 128 rows x 4 segs; thread t -> row t>>1, segs (t&1)*2, (t&1)*2+1 (x2 for h,l)
    // B: 256 rows x 4 segs; thread t -> row t, segs 0..3 (x2 for h,l)
    const int ar = t >> 1, as = (t & 1) * 2;
    const __nv_bfloat16* gAh = Ah + (size_t)(m0 + ar) * K + as * 8;
    const __nv_bfloat16* gAl = Al + (size_t)(m0 + ar) * K + as * 8;
    const __nv_bfloat16* gBh = Bh + (size_t)(n0 + t) * K;
    const __nv_bfloat16* gBl = Bl + (size_t)(n0 + t) * K;
    const uint32_t a0 = swz(ar, as), a1 = swz(ar, as + 1);
    const uint32_t b0 = swz(t, 0), b1 = swz(t, 1), b2 = swz(t, 2), b3 = swz(t, 3);

#define LOAD_CHUNK(k0, base) do {                          \
    cp16((base) + GOFF_AH + a0, gAh + (k0));               \
    cp16((base) + GOFF_AH + a1, gAh + (k0) + 8);           \
    cp16((base) + GOFF_AL + a0, gAl + (k0));               \
    cp16((base) + GOFF_AL + a1, gAl + (k0) + 8);           \
    cp16((base) + GOFF_BH + b0, gBh + (k0));               \
    cp16((base) + GOFF_BH + b1, gBh + (k0) + 8);           \
    cp16((base) + GOFF_BH + b2, gBh + (k0) + 16);          \
    cp16((base) + GOFF_BH + b3, gBh + (k0) + 24);          \
    cp16((base) + GOFF_BL + b0, gBl + (k0));               \
    cp16((base) + GOFF_BL + b1, gBl + (k0) + 8);           \
    cp16((base) + GOFF_BL + b2, gBl + (k0) + 16);          \
    cp16((base) + GOFF_BL + b3, gBl + (k0) + 24);          \
} while (0)

    // ---- compute mapping: warp (wid&1) -> M half, (wid>>1) -> N quarter ----
    const int wm = (wid & 1) * 64;
    const int wn = (wid >> 1) * 64;
    const int arow = wm + (lane & 7) + ((lane >> 3) & 1) * 8;   // A ldsm4 row
    const int aseg = (lane >> 4);                                // 0/1
    const int brow = wn + (lane & 7) + ((lane >> 4) & 1) * 8;    // B ldsm4 row
    const int bseg = (lane >> 3) & 1;                            // 0/1

    float acc[4][8][4];
    #pragma unroll
    for (int i = 0; i < 4; i++)
        #pragma unroll
        for (int j = 0; j < 8; j++)
            #pragma unroll
            for (int v = 0; v < 4; v++) acc[i][j][v] = 0.f;

    const int nch = K / BK;
    LOAD_CHUNK(0, sb);               CP_COMMIT();
    LOAD_CHUNK(BK, sb + GSTAGE);     CP_COMMIT();

    for (int ch = 0; ch < nch; ch++) {
        CP_WAIT1();
        __syncthreads();
        const uint32_t base = sb + (uint32_t)(ch % 3) * GSTAGE;
        // prefetch 2 ahead into the buffer freed at ch-1
        if (ch + 2 < nch) {
            const uint32_t pb = sb + (uint32_t)((ch + 2) % 3) * GSTAGE;
            LOAD_CHUNK((ch + 2) * BK, pb);
        }
        CP_COMMIT();

        #pragma unroll
        for (int ks = 0; ks < 2; ks++) {
            uint32_t ah[4][4], al[4][4];
            #pragma unroll
            for (int mt = 0; mt < 4; mt++) {
                uint32_t off = swz(arow + mt * 16, ks * 2 + aseg);
                ldsm4(ah[mt], base + GOFF_AH + off);
                ldsm4(al[mt], base + GOFF_AL + off);
            }
            #pragma unroll
            for (int np = 0; np < 4; np++) {
                uint32_t bh[4], bl[4];
                uint32_t off = swz(brow + np * 16, ks * 2 + bseg);
                ldsm4(bh, base + GOFF_BH + off);
                ldsm4(bl, base + GOFF_BL + off);
                #pragma unroll
                for (int mt = 0; mt < 4; mt++) {
                    mma16816(acc[mt][np * 2],     ah[mt], bh + 0);
                    mma16816(acc[mt][np * 2],     ah[mt], bl + 0);
                    mma16816(acc[mt][np * 2],     al[mt], bh + 0);
                    mma16816(acc[mt][np * 2 + 1], ah[mt], bh + 2);
                    mma16816(acc[mt][np * 2 + 1], ah[mt], bl + 2);
                    mma16816(acc[mt][np * 2 + 1], al[mt], bh + 2);
                }
            }
        }
        __syncthreads();
    }

    // ---- epilogue ----
    #pragma unroll
    for (int mt = 0; mt < 4; mt++) {
        int r0 = m0 + wm + mt * 16 + (lane >> 2);
        #pragma unroll
        for (int nt = 0; nt < 8; nt++) {
            int c0 = n0 + wn + nt * 8 + (lane & 3) * 2;
            *(float2*)(C + (size_t)r0 * N + c0)       = make_float2(acc[mt][nt][0], acc[mt][nt][1]);
            *(float2*)(C + (size_t)(r0 + 8) * N + c0) = make_float2(acc[mt][nt][2], acc[mt][nt][3]);
        }
    }
#undef LOAD_CHUNK
}

// ============================================================
// conversions
// ============================================================
__global__ void split2(const float* __restrict__ src, __nv_bfloat16* __restrict__ hi,
                       __nv_bfloat16* __restrict__ lo, int n2)
{
    int i = blockIdx.x * blockDim.x + threadIdx.x;
    if (i < n2) {
        float2 v = ((const float2*)src)[i];
        __nv_bfloat16 hx = __float2bfloat16(v.x), hy = __float2bfloat16(v.y);
        float rx = v.x - __bfloat162float(hx);
        float ry = v.y - __bfloat162float(hy);
        ((__nv_bfloat162*)hi)[i] = __halves2bfloat162(hx, hy);
        ((__nv_bfloat162*)lo)[i] = __halves2bfloat162(__float2bfloat16(rx), __float2bfloat16(ry));
    }
}

__global__ void transpose_split(const float* __restrict__ W, __nv_bfloat16* __restrict__ Th,
                                __nv_bfloat16* __restrict__ Tl, int K, int N)
{
    __shared__ float tile[32][33];
    int tx = threadIdx.x, ty = threadIdx.y;
    int n = blockIdx.x * 32 + tx;
    #pragma unroll
    for (int j = 0; j < 4; j++) {
        int k = blockIdx.y * 32 + ty + j * 8;
        tile[ty + j * 8][tx] = W[(size_t)k * N + n];
    }
    __syncthreads();
    int k2 = blockIdx.y * 32 + tx;
    #pragma unroll
    for (int j = 0; j < 4; j++) {
        int n2 = blockIdx.x * 32 + ty + j * 8;
        float v = tile[tx][ty + j * 8];
        __nv_bfloat16 h = __float2bfloat16(v);
        Th[(size_t)n2 * K + k2] = h;
        Tl[(size_t)n2 * K + k2] = __float2bfloat16(v - __bfloat162float(h));
    }
}

// ============================================================
// rope + layout change + hi/lo split
// ============================================================
__global__ void rope_split(const float* __restrict__ q, const float* __restrict__ k,
                           const float* __restrict__ v,
                           const float* __restrict__ cos_, const float* __restrict__ sin_,
                           __nv_bfloat16* qh, __nv_bfloat16* ql,
                           __nv_bfloat16* kh, __nv_bfloat16* kl,
                           __nv_bfloat16* vh, __nv_bfloat16* vl)
{
    const int HD2 = HD / 2;
    const int nqp = BATCH * SEQ * NH * HD2;
    const int nkp = BATCH * SEQ * NKV * HD2;
    const float qscale = 0.08838834764831845f;
    int idx = blockIdx.x * blockDim.x + threadIdx.x;
    if (idx < nqp) {
        int i = idx % HD2;
        int h = (idx / HD2) % NH;
        int s = (idx / (HD2 * NH)) % SEQ;
        int b = idx / (HD2 * NH * SEQ);
        float2 x = *(const float2*)(q + ((size_t)(b * SEQ + s) * NH + h) * HD + 2 * i);
        float c = cos_[s * HD2 + i], sn = sin_[s * HD2 + i];
        float outr = (x.x * c - x.y * sn) * qscale;
        float outi = (x.x * sn + x.y * c) * qscale;
        __nv_bfloat16 hr = __float2bfloat16(outr), hi2 = __float2bfloat16(outi);
        size_t o = ((size_t)(b * NH + h) * SEQ + s) * HD + 2 * i;
        *(__nv_bfloat162*)(qh + o) = __halves2bfloat162(hr, hi2);
        *(__nv_bfloat162*)(ql + o) = __halves2bfloat162(
            __float2bfloat16(outr - __bfloat162float(hr)),
            __float2bfloat16(outi - __bfloat162float(hi2)));
    } else if (idx < nqp + 2 * nkp) {
        int j = idx - nqp;
        int isv = j >= nkp;
        if (isv) j -= nkp;
        int i = j % HD2;
        int h = (j / HD2) % NKV;
        int s = (j / (HD2 * NKV)) % SEQ;
        int b = j / (HD2 * NKV * SEQ);
        const float* src = isv ? v : k;
        float2 x = *(const float2*)(src + ((size_t)(b * SEQ + s) * NKV + h) * HD + 2 * i);
        float outr, outi;
        if (isv) { outr = x.x; outi = x.y; }
        else {
            float c = cos_[s * HD2 + i], sn = sin_[s * HD2 + i];
            outr = x.x * c - x.y * sn;
            outi = x.x * sn + x.y * c;
        }
        __nv_bfloat16 hr = __float2bfloat16(outr), hi2 = __float2bfloat16(outi);
        size_t o = ((size_t)(b * NKV + h) * SEQ + s) * HD + 2 * i;
        __nv_bfloat16* dh = isv ? vh : kh;
        __nv_bfloat16* dl = isv ? vl : kl;
        *(__nv_bfloat162*)(dh + o) = __halves2bfloat162(hr, hi2);
        *(__nv_bfloat162*)(dl + o) = __halves2bfloat162(
            __float2bfloat16(outr - __bfloat162float(hr)),
            __float2bfloat16(outi - __bfloat162float(hi2)));
    }
}

// ============================================================
// flash attention, mma.sync split-bf16 (unchanged from R4, passing)
// ============================================================
#define NTILE (SEQ/64)
#define KVSTG 65536u
#define QOFF  (3u*KVSTG)
#define PH_OFF QOFF
#define PL_OFF (QOFF + 8192u)
#define RED_OFF (QOFF + 16384u)
#define ATT_SMEM (QOFF + 32768u)

__device__ __forceinline__ uint32_t sw256(int row, int boff) {
    return (uint32_t)row * 256u + (uint32_t)(boff ^ ((row & 7) << 4));
}
__device__ __forceinline__ uint32_t sw128(int row, int boff) {
    return (uint32_t)row * 128u + (uint32_t)(boff ^ ((row & 7) << 4));
}

__global__ void __launch_bounds__(256) attn_mma(
    const __nv_bfloat16* __restrict__ qh, const __nv_bfloat16* __restrict__ ql,
    const __nv_bfloat16* __restrict__ kh, const __nv_bfloat16* __restrict__ kl,
    const __nv_bfloat16* __restrict__ vh, const __nv_bfloat16* __restrict__ vl,
    __nv_bfloat16* __restrict__ outh, __nv_bfloat16* __restrict__ outl)
{
    extern __shared__ char sm[];
    const uint32_t sb = smem_u32(sm);
    const int t = threadIdx.x, lane = t & 31, w = t >> 5;
    const int wm = w & 3, wn = w >> 2;
    const int qt = blockIdx.x, h = blockIdx.y, b = blockIdx.z;
    const int kvh = h >> 2;

    const __nv_bfloat16* qhg = qh + ((size_t)(b * NH + h) * SEQ + qt * 64) * HD;
    const __nv_bfloat16* qlg = ql + ((size_t)(b * NH + h) * SEQ + qt * 64) * HD;
    const size_t kvb = (size_t)(b * NKV + kvh) * SEQ * HD;

    {
        int r = t >> 2, seg = t & 3;
        #pragma unroll
        for (int j = 0; j < 4; j++) {
            int boff = seg * 64 + j * 16;
            uint4 a = *(const uint4*)(qhg + (size_t)r * HD + boff / 2);
            *(uint4*)(sm + QOFF + sw256(r, boff)) = a;
            uint4 c = *(const uint4*)(qlg + (size_t)r * HD + boff / 2);
            *(uint4*)(sm + QOFF + 16384u + sw256(r, boff)) = c;
        }
    }

    const int lrow = t >> 2, lseg = t & 3;
#define LOAD_KV(kt, stg) do {                                                   \
    uint32_t bufb = sb + (uint32_t)(stg) * KVSTG;                               \
    size_t grow = kvb + ((size_t)(kt) * 64 + lrow) * HD;                        \
    _Pragma("unroll")                                                           \
    for (int j = 0; j < 4; j++) {                                               \
        int boff = lseg * 64 + j * 16;                                          \
        uint32_t sd = sw256(lrow, boff);                                        \
        cp16(bufb + sd,          kh + grow + boff / 2);                         \
        cp16(bufb + 16384u + sd, kl + grow + boff / 2);                         \
        cp16(bufb + 32768u + sd, vh + grow + boff / 2);                         \
        cp16(bufb + 49152u + sd, vl + grow + boff / 2);                         \
    }                                                                           \
} while (0)

    LOAD_KV(0, 0); CP_COMMIT();
    LOAD_KV(1, 1); CP_COMMIT();
    __syncthreads();

    uint32_t qfh[8][4], qfl[8][4];
    {
        int ar = wm * 16 + (lane & 7) + ((lane >> 3) & 1) * 8;
        int ab = (lane >> 4) * 16;
        #pragma unroll
        for (int ks = 0; ks < 8; ks++) {
            ldsm4(qfh[ks], sb + QOFF + sw256(ar, ks * 32 + ab));
            ldsm4(qfl[ks], sb + QOFF + 16384u + sw256(ar, ks * 32 + ab));
        }
    }

    float m[2] = {-1e30f, -1e30f}, l[2] = {0.f, 0.f};
    float oacc[8][4];
    #pragma unroll
    for (int i = 0; i < 8; i++)
        #pragma unroll
        for (int j = 0; j < 4; j++) oacc[i][j] = 0.f;

    float* redm = (float*)(sm + RED_OFF);
    float* reds = redm + 128;
    const int row1 = wm * 16 + (lane >> 2);
    const int row2 = row1 + 8;

    for (int kt = 0; kt < NTILE; kt++) {
        CP_WAIT1();
        __syncthreads();
        const uint32_t kbuf = sb + (uint32_t)(kt % 3) * KVSTG;
        const uint32_t vbuf = kbuf + 32768u;

        float sacc[4][4];
        #pragma unroll
        for (int i = 0; i < 4; i++)
            #pragma unroll
            for (int j = 0; j < 4; j++) sacc[i][j] = 0.f;
        {
            int br = wn * 32 + (lane & 7) + (lane >> 4) * 8;
            int bb0 = ((lane >> 3) & 1) * 16;
            #pragma unroll
            for (int ks = 0; ks < 8; ks++) {
                #pragma unroll
                for (int np = 0; np < 2; np++) {
                    uint32_t bh[4], bl[4];
                    uint32_t off = sw256(br + np * 16, ks * 32 + bb0);
                    ldsm4(bh, kbuf + off);
                    ldsm4(bl, kbuf + 16384u + off);
                    mma16816(sacc[np * 2],     qfh[ks], bh + 0);
                    mma16816(sacc[np * 2],     qfh[ks], bl + 0);
                    mma16816(sacc[np * 2],     qfl[ks], bh + 0);
                    mma16816(sacc[np * 2 + 1], qfh[ks], bh + 2);
                    mma16816(sacc[np * 2 + 1], qfh[ks], bl + 2);
                    mma16816(sacc[np * 2 + 1], qfl[ks], bh + 2);
                }
            }
        }

        float mx1 = -1e30f, mx2 = -1e30f;
        #pragma unroll
        for (int nt = 0; nt < 4; nt++) {
            mx1 = fmaxf(mx1, fmaxf(sacc[nt][0], sacc[nt][1]));
            mx2 = fmaxf(mx2, fmaxf(sacc[nt][2], sacc[nt][3]));
        }
        mx1 = fmaxf(mx1, __shfl_xor_sync(0xffffffffu, mx1, 1));
        mx1 = fmaxf(mx1, __shfl_xor_sync(0xffffffffu, mx1, 2));
        mx2 = fmaxf(mx2, __shfl_xor_sync(0xffffffffu, mx2, 1));
        mx2 = fmaxf(mx2, __shfl_xor_sync(0xffffffffu, mx2, 2));
        if ((lane & 3) == 0) {
            redm[wn * 64 + row1] = mx1;
            redm[wn * 64 + row2] = mx2;
        }
        __syncthreads();
        if (kt + 2 < NTILE) LOAD_KV(kt + 2, (kt + 2) % 3);
        CP_COMMIT();

        float mn1 = fmaxf(m[0], fmaxf(redm[row1], redm[64 + row1]));
        float mn2 = fmaxf(m[1], fmaxf(redm[row2], redm[64 + row2]));
        float al1 = __expf(m[0] - mn1), al2 = __expf(m[1] - mn2);
        float p[4][4], s1 = 0.f, s2 = 0.f;
        #pragma unroll
        for (int nt = 0; nt < 4; nt++) {
            p[nt][0] = __expf(sacc[nt][0] - mn1);
            p[nt][1] = __expf(sacc[nt][1] - mn1);
            p[nt][2] = __expf(sacc[nt][2] - mn2);
            p[nt][3] = __expf(sacc[nt][3] - mn2);
            s1 += p[nt][0] + p[nt][1];
            s2 += p[nt][2] + p[nt][3];
        }
        s1 += __shfl_xor_sync(0xffffffffu, s1, 1);
        s1 += __shfl_xor_sync(0xffffffffu, s1, 2);
        s2 += __shfl_xor_sync(0xffffffffu, s2, 1);
        s2 += __shfl_xor_sync(0xffffffffu, s2, 2);
        if ((lane & 3) == 0) {
            reds[wn * 64 + row1] = s1;
            reds[wn * 64 + row2] = s2;
        }
        {
            int cb = wn * 64 + (lane & 3) * 4;
            #pragma unroll
            for (int nt = 0; nt < 4; nt++) {
                float h0 = p[nt][0], h1 = p[nt][1], h2 = p[nt][2], h3 = p[nt][3];
                uint32_t ph01 = packbf(h0, h1), ph23 = packbf(h2, h3);
                __nv_bfloat162 b01 = *(__nv_bfloat162*)&ph01;
                __nv_bfloat162 b23 = *(__nv_bfloat162*)&ph23;
                uint32_t pl01 = packbf(h0 - __bfloat162float(b01.x), h1 - __bfloat162float(b01.y));
                uint32_t pl23 = packbf(h2 - __bfloat162float(b23.x), h3 - __bfloat162float(b23.y));
                uint32_t o1 = sw128(row1, cb + nt * 16);
                uint32_t o2 = sw128(row2, cb + nt * 16);
                *(uint32_t*)(sm + PH_OFF + o1) = ph01;
                *(uint32_t*)(sm + PH_OFF + o2) = ph23;
                *(uint32_t*)(sm + PL_OFF + o1) = pl01;
                *(uint32_t*)(sm + PL_OFF + o2) = pl23;
            }
        }
        __syncthreads();
        {
            float tot1 = reds[row1] + reds[64 + row1];
            float tot2 = reds[row2] + reds[64 + row2];
            l[0] = l[0] * al1 + tot1;
            l[1] = l[1] * al2 + tot2;
            m[0] = mn1; m[1] = mn2;
            #pragma unroll
            for (int nt = 0; nt < 8; nt++) {
                oacc[nt][0] *= al1; oacc[nt][1] *= al1;
                oacc[nt][2] *= al2; oacc[nt][3] *= al2;
            }
        }

        {
            int par = wm * 16 + (lane & 7) + ((lane >> 3) & 1) * 8;
            int pab = (lane >> 4) * 16;
            int vr0 = (lane & 7) + ((lane >> 3) & 1) * 8;
            int vb0 = wn * 128 + (lane >> 4) * 16;
            #pragma unroll
            for (int ks = 0; ks < 4; ks++) {
                uint32_t pfh[4], pfl[4];
                ldsm4(pfh, sb + PH_OFF + sw128(par, ks * 32 + pab));
                ldsm4(pfl, sb + PL_OFF + sw128(par, ks * 32 + pab));
                #pragma unroll
                for (int np = 0; np < 4; np++) {
                    uint32_t wh[4], wl[4];
                    uint32_t off = sw256(ks * 16 + vr0, vb0 + np * 32);
                    ldsm4t(wh, vbuf + off);
                    ldsm4t(wl, vbuf + 16384u + off);
                    mma16816(oacc[np * 2],     pfh, wh + 0);
                    mma16816(oacc[np * 2],     pfh, wl + 0);
                    mma16816(oacc[np * 2],     pfl, wh + 0);
                    mma16816(oacc[np * 2 + 1], pfh, wh + 2);
                    mma16816(oacc[np * 2 + 1], pfh, wl + 2);
                    mma16816(oacc[np * 2 + 1], pfl, wh + 2);
                }
            }
        }
        __syncthreads();
    }

    {
        float inv1 = 1.f / l[0], inv2 = 1.f / l[1];
        int rg1 = qt * 64 + row1, rg2 = qt * 64 + row2;
        size_t b1 = ((size_t)(b * SEQ + rg1) * NH + h) * HD;
        size_t b2 = ((size_t)(b * SEQ + rg2) * NH + h) * HD;
        #pragma unroll
        for (int nt = 0; nt < 8; nt++) {
            int c0 = wn * 64 + nt * 8 + (lane & 3) * 2;
            float f0 = oacc[nt][0] * inv1, f1 = oacc[nt][1] * inv1;
            float f2 = oacc[nt][2] * inv2, f3 = oacc[nt][3] * inv2;
            uint32_t h01 = packbf(f0, f1), h23 = packbf(f2, f3);
            __nv_bfloat162 bb01 = *(__nv_bfloat162*)&h01;
            __nv_bfloat162 bb23 = *(__nv_bfloat162*)&h23;
            uint32_t l01 = packbf(f0 - __bfloat162float(bb01.x), f1 - __bfloat162float(bb01.y));
            uint32_t l23 = packbf(f2 - __bfloat162float(bb23.x), f3 - __bfloat162float(bb23.y));
            *(uint32_t*)(outh + b1 + c0) = h01;
            *(uint32_t*)(outh + b2 + c0) = h23;
            *(uint32_t*)(outl + b1 + c0) = l01;
            *(uint32_t*)(outl + b2 + c0) = l23;
        }
    }
#undef LOAD_KV
}

// ============================================================
// launch  (ordered so launch index 3 == gemm_q, for ncu -s 5 -c 1)
// ============================================================
extern "C" void kernel_launch(void* const* d_in, const int* in_sizes, int n_in,
                              void* d_out, int out_size)
{
    const float* x  = (const float*)d_in[0];
    const float* wq = (const float*)d_in[1];
    const float* wk = (const float*)d_in[2];
    const float* wv = (const float*)d_in[3];
    const float* wo = (const float*)d_in[4];
    const float* fcos = (const float*)d_in[7];
    const float* fsin = (const float*)d_in[8];
    float* out = (float*)d_out;

    float *gq, *gk, *gv;
    __nv_bfloat16 *xh, *xl, *wqTh, *wqTl, *wkTh, *wkTl, *wvTh, *wvTl, *woTh, *woTl;
    __nv_bfloat16 *aoh, *aol, *pqh, *pql, *pkh, *pkl, *pvh, *pvl;
    cudaGetSymbolAddress((void**)&gq, g_q);
    cudaGetSymbolAddress((void**)&gk, g_k);
    cudaGetSymbolAddress((void**)&gv, g_v);
    cudaGetSymbolAddress((void**)&xh, g_xh);     cudaGetSymbolAddress((void**)&xl, g_xl);
    cudaGetSymbolAddress((void**)&wqTh, g_wqTh); cudaGetSymbolAddress((void**)&wqTl, g_wqTl);
    cudaGetSymbolAddress((void**)&wkTh, g_wkTh); cudaGetSymbolAddress((void**)&wkTl, g_wkTl);
    cudaGetSymbolAddress((void**)&wvTh, g_wvTh); cudaGetSymbolAddress((void**)&wvTl, g_wvTl);
    cudaGetSymbolAddress((void**)&woTh, g_woTh); cudaGetSymbolAddress((void**)&woTl, g_woTl);
    cudaGetSymbolAddress((void**)&aoh, g_aoh);   cudaGetSymbolAddress((void**)&aol, g_aol);
    cudaGetSymbolAddress((void**)&pqh, g_qh);    cudaGetSymbolAddress((void**)&pql, g_ql);
    cudaGetSymbolAddress((void**)&pkh, g_kh);    cudaGetSymbolAddress((void**)&pkl, g_kl);
    cudaGetSymbolAddress((void**)&pvh, g_vh);    cudaGetSymbolAddress((void**)&pvl, g_vl);

    cudaFuncSetAttribute(gemm_mma256, cudaFuncAttributeMaxDynamicSharedMemorySize, GEMM_SMEM);
    cudaFuncSetAttribute(attn_mma, cudaFuncAttributeMaxDynamicSharedMemorySize, ATT_SMEM);

    // 0: split x
    {
        int n2 = (int)((size_t)MTOT * DIM / 2);
        split2<<<(n2 + 255) / 256, 256>>>(x, xh, xl, n2);
    }
    // 1,2: wq, wk transpose
    transpose_split<<<dim3(NQ / 32, DIM / 32),   dim3(32, 8)>>>(wq, wqTh, wqTl, DIM, NQ);
    transpose_split<<<dim3(NKVD / 32, DIM / 32), dim3(32, 8)>>>(wk, wkTh, wkTl, DIM, NKVD);
    // 3: gemm_q  <-- ncu capture slot
    gemm_mma256<<<dim3(NQ / BN, MTOT / BM), 256, GEMM_SMEM>>>(xh, xl, wqTh, wqTl, gq, MTOT, NQ, DIM);
    // 4: wv transpose, 5: gemm_k, 6: gemm_v, 7: wo transpose
    transpose_split<<<dim3(NKVD / 32, DIM / 32), dim3(32, 8)>>>(wv, wvTh, wvTl, DIM, NKVD);
    gemm_mma256<<<dim3(NKVD / BN, MTOT / BM), 256, GEMM_SMEM>>>(xh, xl, wkTh, wkTl, gk, MTOT, NKVD, DIM);
    gemm_mma256<<<dim3(NKVD / BN, MTOT / BM), 256, GEMM_SMEM>>>(xh, xl, wvTh, wvTl, gv, MTOT, NKVD, DIM);
    transpose_split<<<dim3(DIM / 32, NQ / 32),   dim3(32, 8)>>>(wo, woTh, woTl, NQ, DIM);

    // 8: rope + split + relayout
    {
        int total = BATCH * SEQ * (NH + 2 * NKV) * (HD / 2);
        rope_split<<<(total + 255) / 256, 256>>>(gq, gk, gv, fcos, fsin,
                                                 pqh, pql, pkh, pkl, pvh, pvl);
    }
    // 9: attention
    {
        dim3 grid(SEQ / 64, NH, BATCH);
        attn_mma<<<grid, 256, ATT_SMEM>>>(pqh, pql, pkh, pkl, pvh, pvl, aoh, aol);
    }
    // 10: output projection
    gemm_mma256<<<dim3(DIM / BN, MTOT / BM), 256, GEMM_SMEM>>>(aoh, aol, woTh, woTl, out, MTOT, DIM, NQ);
}

// round 6
// speedup vs baseline: 1.1254x; 1.1254x over previous
#include <cuda_runtime.h>
#include <cuda_bf16.h>
#include <cstdint>
#include <math.h>

#define BATCH 2
#define SEQ   2048
#define DIM   4096
#define NH    32
#define NKV   8
#define HD    128
#define NREP  4
#define MTOT  (BATCH*SEQ)   // 4096
#define NQ    (NH*HD)       // 4096
#define NKVD  (NKV*HD)      // 1024

// -------- scratch (device globals) --------
__device__ float g_q[(size_t)MTOT*NQ];
__device__ float g_k[(size_t)MTOT*NKVD];
__device__ float g_v[(size_t)MTOT*NKVD];

__device__ __nv_bfloat16 g_xh[(size_t)MTOT*DIM],  g_xl[(size_t)MTOT*DIM];
__device__ __nv_bfloat16 g_wqTh[(size_t)NQ*DIM],  g_wqTl[(size_t)NQ*DIM];
__device__ __nv_bfloat16 g_wkTh[(size_t)NKVD*DIM],g_wkTl[(size_t)NKVD*DIM];
__device__ __nv_bfloat16 g_wvTh[(size_t)NKVD*DIM],g_wvTl[(size_t)NKVD*DIM];
__device__ __nv_bfloat16 g_woTh[(size_t)DIM*NQ],  g_woTl[(size_t)DIM*NQ];
__device__ __nv_bfloat16 g_aoh[(size_t)MTOT*NQ],  g_aol[(size_t)MTOT*NQ];
__device__ __nv_bfloat16 g_qh[(size_t)MTOT*NQ],   g_ql[(size_t)MTOT*NQ];
__device__ __nv_bfloat16 g_kh[(size_t)MTOT*NKVD], g_kl[(size_t)MTOT*NKVD];
__device__ __nv_bfloat16 g_vh[(size_t)MTOT*NKVD], g_vl[(size_t)MTOT*NKVD];

// ============================================================
// PTX helpers
// ============================================================
__device__ __forceinline__ uint32_t smem_u32(const void* p) {
    uint32_t a;
    asm("{ .reg .u64 t; cvta.to.shared.u64 t, %1; cvt.u32.u64 %0, t; }" : "=r"(a) : "l"(p));
    return a;
}
__device__ __forceinline__ void cp16(uint32_t dst, const void* src) {
    asm volatile("cp.async.cg.shared.global [%0], [%1], 16;" :: "r"(dst), "l"(src));
}
#define CP_COMMIT()  asm volatile("cp.async.commit_group;")
#define CP_WAIT1()   asm volatile("cp.async.wait_group 1;")

__device__ __forceinline__ void ldsm4(uint32_t* r, uint32_t addr) {
    asm volatile("ldmatrix.sync.aligned.m8n8.x4.shared.b16 {%0,%1,%2,%3}, [%4];"
        : "=r"(r[0]), "=r"(r[1]), "=r"(r[2]), "=r"(r[3]) : "r"(addr));
}
__device__ __forceinline__ void ldsm4t(uint32_t* r, uint32_t addr) {
    asm volatile("ldmatrix.sync.aligned.m8n8.x4.trans.shared.b16 {%0,%1,%2,%3}, [%4];"
        : "=r"(r[0]), "=r"(r[1]), "=r"(r[2]), "=r"(r[3]) : "r"(addr));
}
__device__ __forceinline__ void mma16816(float* c, const uint32_t* a, const uint32_t* b) {
    asm volatile("mma.sync.aligned.m16n8k16.row.col.f32.bf16.bf16.f32 "
        "{%0,%1,%2,%3}, {%4,%5,%6,%7}, {%8,%9}, {%0,%1,%2,%3};"
        : "+f"(c[0]), "+f"(c[1]), "+f"(c[2]), "+f"(c[3])
        : "r"(a[0]), "r"(a[1]), "r"(a[2]), "r"(a[3]), "r"(b[0]), "r"(b[1]));
}
__device__ __forceinline__ uint32_t packbf(float a, float b) {
    __nv_bfloat162 v = __floats2bfloat162_rn(a, b);
    return *(uint32_t*)&v;
}

// swizzles: XOR seg with low row bits; rows of 256B / 128B
__device__ __forceinline__ uint32_t sw256(int row, int boff) {
    return (uint32_t)row * 256u + (uint32_t)(boff ^ ((row & 7) << 4));
}
__device__ __forceinline__ uint32_t sw128(int row, int boff) {
    return (uint32_t)row * 128u + (uint32_t)(boff ^ ((row & 7) << 4));
}

// ============================================================
// split-bf16 GEMM v3: CTA 128x128, BK=64, warp tile 64x32 (8 warps 2x4),
// 3-stage cp.async ring, ONE barrier per chunk.
// C[M,N] = (Ah+Al)[M,K] @ (Bh+Bl)[N,K]^T
// ============================================================
#define BM 128
#define BN 128
#define BK 64
#define GOFF_AH 0u
#define GOFF_AL 16384u
#define GOFF_BH 32768u
#define GOFF_BL 49152u
#define GSTAGE  65536u
#define GEMM_SMEM (3*65536)

__global__ void __launch_bounds__(256, 1) gemm_mma(
    const __nv_bfloat16* __restrict__ Ah, const __nv_bfloat16* __restrict__ Al,
    const __nv_bfloat16* __restrict__ Bh, const __nv_bfloat16* __restrict__ Bl,
    float* __restrict__ C, int M, int N, int K)
{
    extern __shared__ char smem[];
    const uint32_t sb = smem_u32(smem);
    const int t = threadIdx.x;
    const int lane = t & 31, wid = t >> 5;
    const int m0 = blockIdx.y * BM, n0 = blockIdx.x * BN;

    // ---- loader: thread t -> row t>>1, 4 consecutive 16B segs at (t&1)*64B ----
    const int lrow = t >> 1;
    const int lhalf = (t & 1) * 4;                 // seg base (16B units)
    const __nv_bfloat16* gAh = Ah + (size_t)(m0 + lrow) * K + lhalf * 8;
    const __nv_bfloat16* gAl = Al + (size_t)(m0 + lrow) * K + lhalf * 8;
    const __nv_bfloat16* gBh = Bh + (size_t)(n0 + lrow) * K + lhalf * 8;
    const __nv_bfloat16* gBl = Bl + (size_t)(n0 + lrow) * K + lhalf * 8;
    uint32_t loffs[4];
    #pragma unroll
    for (int j = 0; j < 4; j++) loffs[j] = sw128(lrow, (lhalf + j) * 16);

#define LOAD_CHUNK(k0, base) do {                                  \
    _Pragma("unroll")                                              \
    for (int j = 0; j < 4; j++) {                                  \
        cp16((base) + GOFF_AH + loffs[j], gAh + (k0) + j * 8);     \
        cp16((base) + GOFF_AL + loffs[j], gAl + (k0) + j * 8);     \
        cp16((base) + GOFF_BH + loffs[j], gBh + (k0) + j * 8);     \
        cp16((base) + GOFF_BL + loffs[j], gBl + (k0) + j * 8);     \
    }                                                              \
} while (0)

    // ---- compute mapping: warp tile 64(M) x 32(N) ----
    const int wm = (wid >> 2) * 64;
    const int wn = (wid & 3) * 32;
    const int arow = wm + (lane & 7) + ((lane >> 3) & 1) * 8;
    const int acol = (lane >> 4) * 16;             // byte offset within 32B k-block
    const int brow = wn + (lane & 7) + ((lane >> 4) & 1) * 8;
    const int bcol = ((lane >> 3) & 1) * 16;

    float acc[4][4][4];
    #pragma unroll
    for (int i = 0; i < 4; i++)
        #pragma unroll
        for (int j = 0; j < 4; j++)
            #pragma unroll
            for (int v = 0; v < 4; v++) acc[i][j][v] = 0.f;

    const int nch = K / BK;                        // 64
    LOAD_CHUNK(0, sb);                CP_COMMIT();
    LOAD_CHUNK(BK, sb + GSTAGE);      CP_COMMIT();

    for (int ch = 0; ch < nch; ch++) {
        CP_WAIT1();
        __syncthreads();                           // single barrier per chunk
        const uint32_t base = sb + (uint32_t)(ch % 3) * GSTAGE;
        if (ch + 2 < nch) {
            const uint32_t pb = sb + (uint32_t)((ch + 2) % 3) * GSTAGE;
            LOAD_CHUNK((ch + 2) * BK, pb);
        }
        CP_COMMIT();

        #pragma unroll
        for (int ks = 0; ks < 4; ks++) {           // 16 cols (32B) per step
            uint32_t ah[4][4], al[4][4], bh[2][4], bl[2][4];
            #pragma unroll
            for (int mt = 0; mt < 4; mt++) {
                uint32_t off = sw128(arow + mt * 16, ks * 32 + acol);
                ldsm4(ah[mt], base + GOFF_AH + off);
                ldsm4(al[mt], base + GOFF_AL + off);
            }
            #pragma unroll
            for (int np = 0; np < 2; np++) {
                uint32_t off = sw128(brow + np * 16, ks * 32 + bcol);
                ldsm4(bh[np], base + GOFF_BH + off);
                ldsm4(bl[np], base + GOFF_BL + off);
            }
            #pragma unroll
            for (int np = 0; np < 2; np++)
                #pragma unroll
                for (int mt = 0; mt < 4; mt++) {
                    mma16816(acc[mt][np * 2],     ah[mt], bh[np] + 0);
                    mma16816(acc[mt][np * 2],     ah[mt], bl[np] + 0);
                    mma16816(acc[mt][np * 2],     al[mt], bh[np] + 0);
                    mma16816(acc[mt][np * 2 + 1], ah[mt], bh[np] + 2);
                    mma16816(acc[mt][np * 2 + 1], ah[mt], bl[np] + 2);
                    mma16816(acc[mt][np * 2 + 1], al[mt], bh[np] + 2);
                }
        }
    }

    // ---- epilogue ----
    #pragma unroll
    for (int mt = 0; mt < 4; mt++) {
        int r0 = m0 + wm + mt * 16 + (lane >> 2);
        #pragma unroll
        for (int nt = 0; nt < 4; nt++) {
            int c0 = n0 + wn + nt * 8 + (lane & 3) * 2;
            *(float2*)(C + (size_t)r0 * N + c0)       = make_float2(acc[mt][nt][0], acc[mt][nt][1]);
            *(float2*)(C + (size_t)(r0 + 8) * N + c0) = make_float2(acc[mt][nt][2], acc[mt][nt][3]);
        }
    }
#undef LOAD_CHUNK
}

// ============================================================
// conversions
// ============================================================
__global__ void split2(const float* __restrict__ src, __nv_bfloat16* __restrict__ hi,
                       __nv_bfloat16* __restrict__ lo, int n2)
{
    int i = blockIdx.x * blockDim.x + threadIdx.x;
    if (i < n2) {
        float2 v = ((const float2*)src)[i];
        __nv_bfloat16 hx = __float2bfloat16(v.x), hy = __float2bfloat16(v.y);
        float rx = v.x - __bfloat162float(hx);
        float ry = v.y - __bfloat162float(hy);
        ((__nv_bfloat162*)hi)[i] = __halves2bfloat162(hx, hy);
        ((__nv_bfloat162*)lo)[i] = __halves2bfloat162(__float2bfloat16(rx), __float2bfloat16(ry));
    }
}

__global__ void transpose_split(const float* __restrict__ W, __nv_bfloat16* __restrict__ Th,
                                __nv_bfloat16* __restrict__ Tl, int K, int N)
{
    __shared__ float tile[32][33];
    int tx = threadIdx.x, ty = threadIdx.y;
    int n = blockIdx.x * 32 + tx;
    #pragma unroll
    for (int j = 0; j < 4; j++) {
        int k = blockIdx.y * 32 + ty + j * 8;
        tile[ty + j * 8][tx] = W[(size_t)k * N + n];
    }
    __syncthreads();
    int k2 = blockIdx.y * 32 + tx;
    #pragma unroll
    for (int j = 0; j < 4; j++) {
        int n2 = blockIdx.x * 32 + ty + j * 8;
        float v = tile[tx][ty + j * 8];
        __nv_bfloat16 h = __float2bfloat16(v);
        Th[(size_t)n2 * K + k2] = h;
        Tl[(size_t)n2 * K + k2] = __float2bfloat16(v - __bfloat162float(h));
    }
}

// ============================================================
// rope + layout change + hi/lo split
// ============================================================
__global__ void rope_split(const float* __restrict__ q, const float* __restrict__ k,
                           const float* __restrict__ v,
                           const float* __restrict__ cos_, const float* __restrict__ sin_,
                           __nv_bfloat16* qh, __nv_bfloat16* ql,
                           __nv_bfloat16* kh, __nv_bfloat16* kl,
                           __nv_bfloat16* vh, __nv_bfloat16* vl)
{
    const int HD2 = HD / 2;
    const int nqp = BATCH * SEQ * NH * HD2;
    const int nkp = BATCH * SEQ * NKV * HD2;
    const float qscale = 0.08838834764831845f;
    int idx = blockIdx.x * blockDim.x + threadIdx.x;
    if (idx < nqp) {
        int i = idx % HD2;
        int h = (idx / HD2) % NH;
        int s = (idx / (HD2 * NH)) % SEQ;
        int b = idx / (HD2 * NH * SEQ);
        float2 x = *(const float2*)(q + ((size_t)(b * SEQ + s) * NH + h) * HD + 2 * i);
        float c = cos_[s * HD2 + i], sn = sin_[s * HD2 + i];
        float outr = (x.x * c - x.y * sn) * qscale;
        float outi = (x.x * sn + x.y * c) * qscale;
        __nv_bfloat16 hr = __float2bfloat16(outr), hi2 = __float2bfloat16(outi);
        size_t o = ((size_t)(b * NH + h) * SEQ + s) * HD + 2 * i;
        *(__nv_bfloat162*)(qh + o) = __halves2bfloat162(hr, hi2);
        *(__nv_bfloat162*)(ql + o) = __halves2bfloat162(
            __float2bfloat16(outr - __bfloat162float(hr)),
            __float2bfloat16(outi - __bfloat162float(hi2)));
    } else if (idx < nqp + 2 * nkp) {
        int j = idx - nqp;
        int isv = j >= nkp;
        if (isv) j -= nkp;
        int i = j % HD2;
        int h = (j / HD2) % NKV;
        int s = (j / (HD2 * NKV)) % SEQ;
        int b = j / (HD2 * NKV * SEQ);
        const float* src = isv ? v : k;
        float2 x = *(const float2*)(src + ((size_t)(b * SEQ + s) * NKV + h) * HD + 2 * i);
        float outr, outi;
        if (isv) { outr = x.x; outi = x.y; }
        else {
            float c = cos_[s * HD2 + i], sn = sin_[s * HD2 + i];
            outr = x.x * c - x.y * sn;
            outi = x.x * sn + x.y * c;
        }
        __nv_bfloat16 hr = __float2bfloat16(outr), hi2 = __float2bfloat16(outi);
        size_t o = ((size_t)(b * NKV + h) * SEQ + s) * HD + 2 * i;
        __nv_bfloat16* dh = isv ? vh : kh;
        __nv_bfloat16* dl = isv ? vl : kl;
        *(__nv_bfloat162*)(dh + o) = __halves2bfloat162(hr, hi2);
        *(__nv_bfloat162*)(dl + o) = __halves2bfloat162(
            __float2bfloat16(outr - __bfloat162float(hr)),
            __float2bfloat16(outi - __bfloat162float(hi2)));
    }
}

// ============================================================
// flash attention, mma.sync split-bf16 (unchanged from R4, passing)
// ============================================================
#define NTILE (SEQ/64)
#define KVSTG 65536u
#define QOFF  (3u*KVSTG)
#define PH_OFF QOFF
#define PL_OFF (QOFF + 8192u)
#define RED_OFF (QOFF + 16384u)
#define ATT_SMEM (QOFF + 32768u)

__global__ void __launch_bounds__(256) attn_mma(
    const __nv_bfloat16* __restrict__ qh, const __nv_bfloat16* __restrict__ ql,
    const __nv_bfloat16* __restrict__ kh, const __nv_bfloat16* __restrict__ kl,
    const __nv_bfloat16* __restrict__ vh, const __nv_bfloat16* __restrict__ vl,
    __nv_bfloat16* __restrict__ outh, __nv_bfloat16* __restrict__ outl)
{
    extern __shared__ char sm[];
    const uint32_t sb = smem_u32(sm);
    const int t = threadIdx.x, lane = t & 31, w = t >> 5;
    const int wm = w & 3, wn = w >> 2;
    const int qt = blockIdx.x, h = blockIdx.y, b = blockIdx.z;
    const int kvh = h >> 2;

    const __nv_bfloat16* qhg = qh + ((size_t)(b * NH + h) * SEQ + qt * 64) * HD;
    const __nv_bfloat16* qlg = ql + ((size_t)(b * NH + h) * SEQ + qt * 64) * HD;
    const size_t kvb = (size_t)(b * NKV + kvh) * SEQ * HD;

    {
        int r = t >> 2, seg = t & 3;
        #pragma unroll
        for (int j = 0; j < 4; j++) {
            int boff = seg * 64 + j * 16;
            uint4 a = *(const uint4*)(qhg + (size_t)r * HD + boff / 2);
            *(uint4*)(sm + QOFF + sw256(r, boff)) = a;
            uint4 c = *(const uint4*)(qlg + (size_t)r * HD + boff / 2);
            *(uint4*)(sm + QOFF + 16384u + sw256(r, boff)) = c;
        }
    }

    const int lrow = t >> 2, lseg = t & 3;
#define LOAD_KV(kt, stg) do {                                                   \
    uint32_t bufb = sb + (uint32_t)(stg) * KVSTG;                               \
    size_t grow = kvb + ((size_t)(kt) * 64 + lrow) * HD;                        \
    _Pragma("unroll")                                                           \
    for (int j = 0; j < 4; j++) {                                               \
        int boff = lseg * 64 + j * 16;                                          \
        uint32_t sd = sw256(lrow, boff);                                        \
        cp16(bufb + sd,          kh + grow + boff / 2);                         \
        cp16(bufb + 16384u + sd, kl + grow + boff / 2);                         \
        cp16(bufb + 32768u + sd, vh + grow + boff / 2);                         \
        cp16(bufb + 49152u + sd, vl + grow + boff / 2);                         \
    }                                                                           \
} while (0)

    LOAD_KV(0, 0); CP_COMMIT();
    LOAD_KV(1, 1); CP_COMMIT();
    __syncthreads();

    uint32_t qfh[8][4], qfl[8][4];
    {
        int ar = wm * 16 + (lane & 7) + ((lane >> 3) & 1) * 8;
        int ab = (lane >> 4) * 16;
        #pragma unroll
        for (int ks = 0; ks < 8; ks++) {
            ldsm4(qfh[ks], sb + QOFF + sw256(ar, ks * 32 + ab));
            ldsm4(qfl[ks], sb + QOFF + 16384u + sw256(ar, ks * 32 + ab));
        }
    }

    float m[2] = {-1e30f, -1e30f}, l[2] = {0.f, 0.f};
    float oacc[8][4];
    #pragma unroll
    for (int i = 0; i < 8; i++)
        #pragma unroll
        for (int j = 0; j < 4; j++) oacc[i][j] = 0.f;

    float* redm = (float*)(sm + RED_OFF);
    float* reds = redm + 128;
    const int row1 = wm * 16 + (lane >> 2);
    const int row2 = row1 + 8;

    for (int kt = 0; kt < NTILE; kt++) {
        CP_WAIT1();
        __syncthreads();
        const uint32_t kbuf = sb + (uint32_t)(kt % 3) * KVSTG;
        const uint32_t vbuf = kbuf + 32768u;

        float sacc[4][4];
        #pragma unroll
        for (int i = 0; i < 4; i++)
            #pragma unroll
            for (int j = 0; j < 4; j++) sacc[i][j] = 0.f;
        {
            int br = wn * 32 + (lane & 7) + (lane >> 4) * 8;
            int bb0 = ((lane >> 3) & 1) * 16;
            #pragma unroll
            for (int ks = 0; ks < 8; ks++) {
                #pragma unroll
                for (int np = 0; np < 2; np++) {
                    uint32_t bh[4], bl[4];
                    uint32_t off = sw256(br + np * 16, ks * 32 + bb0);
                    ldsm4(bh, kbuf + off);
                    ldsm4(bl, kbuf + 16384u + off);
                    mma16816(sacc[np * 2],     qfh[ks], bh + 0);
                    mma16816(sacc[np * 2],     qfh[ks], bl + 0);
                    mma16816(sacc[np * 2],     qfl[ks], bh + 0);
                    mma16816(sacc[np * 2 + 1], qfh[ks], bh + 2);
                    mma16816(sacc[np * 2 + 1], qfh[ks], bl + 2);
                    mma16816(sacc[np * 2 + 1], qfl[ks], bh + 2);
                }
            }
        }

        float mx1 = -1e30f, mx2 = -1e30f;
        #pragma unroll
        for (int nt = 0; nt < 4; nt++) {
            mx1 = fmaxf(mx1, fmaxf(sacc[nt][0], sacc[nt][1]));
            mx2 = fmaxf(mx2, fmaxf(sacc[nt][2], sacc[nt][3]));
        }
        mx1 = fmaxf(mx1, __shfl_xor_sync(0xffffffffu, mx1, 1));
        mx1 = fmaxf(mx1, __shfl_xor_sync(0xffffffffu, mx1, 2));
        mx2 = fmaxf(mx2, __shfl_xor_sync(0xffffffffu, mx2, 1));
        mx2 = fmaxf(mx2, __shfl_xor_sync(0xffffffffu, mx2, 2));
        if ((lane & 3) == 0) {
            redm[wn * 64 + row1] = mx1;
            redm[wn * 64 + row2] = mx2;
        }
        __syncthreads();
        if (kt + 2 < NTILE) LOAD_KV(kt + 2, (kt + 2) % 3);
        CP_COMMIT();

        float mn1 = fmaxf(m[0], fmaxf(redm[row1], redm[64 + row1]));
        float mn2 = fmaxf(m[1], fmaxf(redm[row2], redm[64 + row2]));
        float al1 = __expf(m[0] - mn1), al2 = __expf(m[1] - mn2);
        float p[4][4], s1 = 0.f, s2 = 0.f;
        #pragma unroll
        for (int nt = 0; nt < 4; nt++) {
            p[nt][0] = __expf(sacc[nt][0] - mn1);
            p[nt][1] = __expf(sacc[nt][1] - mn1);
            p[nt][2] = __expf(sacc[nt][2] - mn2);
            p[nt][3] = __expf(sacc[nt][3] - mn2);
            s1 += p[nt][0] + p[nt][1];
            s2 += p[nt][2] + p[nt][3];
        }
        s1 += __shfl_xor_sync(0xffffffffu, s1, 1);
        s1 += __shfl_xor_sync(0xffffffffu, s1, 2);
        s2 += __shfl_xor_sync(0xffffffffu, s2, 1);
        s2 += __shfl_xor_sync(0xffffffffu, s2, 2);
        if ((lane & 3) == 0) {
            reds[wn * 64 + row1] = s1;
            reds[wn * 64 + row2] = s2;
        }
        {
            int cb = wn * 64 + (lane & 3) * 4;
            #pragma unroll
            for (int nt = 0; nt < 4; nt++) {
                float h0 = p[nt][0], h1 = p[nt][1], h2 = p[nt][2], h3 = p[nt][3];
                uint32_t ph01 = packbf(h0, h1), ph23 = packbf(h2, h3);
                __nv_bfloat162 b01 = *(__nv_bfloat162*)&ph01;
                __nv_bfloat162 b23 = *(__nv_bfloat162*)&ph23;
                uint32_t pl01 = packbf(h0 - __bfloat162float(b01.x), h1 - __bfloat162float(b01.y));
                uint32_t pl23 = packbf(h2 - __bfloat162float(b23.x), h3 - __bfloat162float(b23.y));
                uint32_t o1 = sw128(row1, cb + nt * 16);
                uint32_t o2 = sw128(row2, cb + nt * 16);
                *(uint32_t*)(sm + PH_OFF + o1) = ph01;
                *(uint32_t*)(sm + PH_OFF + o2) = ph23;
                *(uint32_t*)(sm + PL_OFF + o1) = pl01;
                *(uint32_t*)(sm + PL_OFF + o2) = pl23;
            }
        }
        __syncthreads();
        {
            float tot1 = reds[row1] + reds[64 + row1];
            float tot2 = reds[row2] + reds[64 + row2];
            l[0] = l[0] * al1 + tot1;
            l[1] = l[1] * al2 + tot2;
            m[0] = mn1; m[1] = mn2;
            #pragma unroll
            for (int nt = 0; nt < 8; nt++) {
                oacc[nt][0] *= al1; oacc[nt][1] *= al1;
                oacc[nt][2] *= al2; oacc[nt][3] *= al2;
            }
        }

        {
            int par = wm * 16 + (lane & 7) + ((lane >> 3) & 1) * 8;
            int pab = (lane >> 4) * 16;
            int vr0 = (lane & 7) + ((lane >> 3) & 1) * 8;
            int vb0 = wn * 128 + (lane >> 4) * 16;
            #pragma unroll
            for (int ks = 0; ks < 4; ks++) {
                uint32_t pfh[4], pfl[4];
                ldsm4(pfh, sb + PH_OFF + sw128(par, ks * 32 + pab));
                ldsm4(pfl, sb + PL_OFF + sw128(par, ks * 32 + pab));
                #pragma unroll
                for (int np = 0; np < 4; np++) {
                    uint32_t wh[4], wl[4];
                    uint32_t off = sw256(ks * 16 + vr0, vb0 + np * 32);
                    ldsm4t(wh, vbuf + off);
                    ldsm4t(wl, vbuf + 16384u + off);
                    mma16816(oacc[np * 2],     pfh, wh + 0);
                    mma16816(oacc[np * 2],     pfh, wl + 0);
                    mma16816(oacc[np * 2],     pfl, wh + 0);
                    mma16816(oacc[np * 2 + 1], pfh, wh + 2);
                    mma16816(oacc[np * 2 + 1], pfh, wl + 2);
                    mma16816(oacc[np * 2 + 1], pfl, wh + 2);
                }
            }
        }
        __syncthreads();
    }

    {
        float inv1 = 1.f / l[0], inv2 = 1.f / l[1];
        int rg1 = qt * 64 + row1, rg2 = qt * 64 + row2;
        size_t b1 = ((size_t)(b * SEQ + rg1) * NH + h) * HD;
        size_t b2 = ((size_t)(b * SEQ + rg2) * NH + h) * HD;
        #pragma unroll
        for (int nt = 0; nt < 8; nt++) {
            int c0 = wn * 64 + nt * 8 + (lane & 3) * 2;
            float f0 = oacc[nt][0] * inv1, f1 = oacc[nt][1] * inv1;
            float f2 = oacc[nt][2] * inv2, f3 = oacc[nt][3] * inv2;
            uint32_t h01 = packbf(f0, f1), h23 = packbf(f2, f3);
            __nv_bfloat162 bb01 = *(__nv_bfloat162*)&h01;
            __nv_bfloat162 bb23 = *(__nv_bfloat162*)&h23;
            uint32_t l01 = packbf(f0 - __bfloat162float(bb01.x), f1 - __bfloat162float(bb01.y));
            uint32_t l23 = packbf(f2 - __bfloat162float(bb23.x), f3 - __bfloat162float(bb23.y));
            *(uint32_t*)(outh + b1 + c0) = h01;
            *(uint32_t*)(outh + b2 + c0) = h23;
            *(uint32_t*)(outl + b1 + c0) = l01;
            *(uint32_t*)(outl + b2 + c0) = l23;
        }
    }
#undef LOAD_KV
}

// ============================================================
// launch  (gemm_q at launch index 3 for ncu -s 5 -c 1)
// ============================================================
extern "C" void kernel_launch(void* const* d_in, const int* in_sizes, int n_in,
                              void* d_out, int out_size)
{
    const float* x  = (const float*)d_in[0];
    const float* wq = (const float*)d_in[1];
    const float* wk = (const float*)d_in[2];
    const float* wv = (const float*)d_in[3];
    const float* wo = (const float*)d_in[4];
    const float* fcos = (const float*)d_in[7];
    const float* fsin = (const float*)d_in[8];
    float* out = (float*)d_out;

    float *gq, *gk, *gv;
    __nv_bfloat16 *xh, *xl, *wqTh, *wqTl, *wkTh, *wkTl, *wvTh, *wvTl, *woTh, *woTl;
    __nv_bfloat16 *aoh, *aol, *pqh, *pql, *pkh, *pkl, *pvh, *pvl;
    cudaGetSymbolAddress((void**)&gq, g_q);
    cudaGetSymbolAddress((void**)&gk, g_k);
    cudaGetSymbolAddress((void**)&gv, g_v);
    cudaGetSymbolAddress((void**)&xh, g_xh);     cudaGetSymbolAddress((void**)&xl, g_xl);
    cudaGetSymbolAddress((void**)&wqTh, g_wqTh); cudaGetSymbolAddress((void**)&wqTl, g_wqTl);
    cudaGetSymbolAddress((void**)&wkTh, g_wkTh); cudaGetSymbolAddress((void**)&wkTl, g_wkTl);
    cudaGetSymbolAddress((void**)&wvTh, g_wvTh); cudaGetSymbolAddress((void**)&wvTl, g_wvTl);
    cudaGetSymbolAddress((void**)&woTh, g_woTh); cudaGetSymbolAddress((void**)&woTl, g_woTl);
    cudaGetSymbolAddress((void**)&aoh, g_aoh);   cudaGetSymbolAddress((void**)&aol, g_aol);
    cudaGetSymbolAddress((void**)&pqh, g_qh);    cudaGetSymbolAddress((void**)&pql, g_ql);
    cudaGetSymbolAddress((void**)&pkh, g_kh);    cudaGetSymbolAddress((void**)&pkl, g_kl);
    cudaGetSymbolAddress((void**)&pvh, g_vh);    cudaGetSymbolAddress((void**)&pvl, g_vl);

    cudaFuncSetAttribute(gemm_mma, cudaFuncAttributeMaxDynamicSharedMemorySize, GEMM_SMEM);
    cudaFuncSetAttribute(attn_mma, cudaFuncAttributeMaxDynamicSharedMemorySize, ATT_SMEM);

    // 0: split x
    {
        int n2 = (int)((size_t)MTOT * DIM / 2);
        split2<<<(n2 + 255) / 256, 256>>>(x, xh, xl, n2);
    }
    // 1,2: wq, wk transpose
    transpose_split<<<dim3(NQ / 32, DIM / 32),   dim3(32, 8)>>>(wq, wqTh, wqTl, DIM, NQ);
    transpose_split<<<dim3(NKVD / 32, DIM / 32), dim3(32, 8)>>>(wk, wkTh, wkTl, DIM, NKVD);
    // 3: gemm_q  <-- ncu capture slot
    gemm_mma<<<dim3(NQ / BN, MTOT / BM), 256, GEMM_SMEM>>>(xh, xl, wqTh, wqTl, gq, MTOT, NQ, DIM);
    // 4..7
    transpose_split<<<dim3(NKVD / 32, DIM / 32), dim3(32, 8)>>>(wv, wvTh, wvTl, DIM, NKVD);
    gemm_mma<<<dim3(NKVD / BN, MTOT / BM), 256, GEMM_SMEM>>>(xh, xl, wkTh, wkTl, gk, MTOT, NKVD, DIM);
    gemm_mma<<<dim3(NKVD / BN, MTOT / BM), 256, GEMM_SMEM>>>(xh, xl, wvTh, wvTl, gv, MTOT, NKVD, DIM);
    transpose_split<<<dim3(DIM / 32, NQ / 32),   dim3(32, 8)>>>(wo, woTh, woTl, NQ, DIM);

    // 8: rope + split + relayout
    {
        int total = BATCH * SEQ * (NH + 2 * NKV) * (HD / 2);
        rope_split<<<(total + 255) / 256, 256>>>(gq, gk, gv, fcos, fsin,
                                                 pqh, pql, pkh, pkl, pvh, pvl);
    }
    // 9: attention
    {
        dim3 grid(SEQ / 64, NH, BATCH);
        attn_mma<<<grid, 256, ATT_SMEM>>>(pqh, pql, pkh, pkl, pvh, pvl, aoh, aol);
    }
    // 10: output projection
    gemm_mma<<<dim3(DIM / BN, MTOT / BM), 256, GEMM_SMEM>>>(aoh, aol, woTh, woTl, out, MTOT, DIM, NQ);
}

// round 7
// speedup vs baseline: 1.3322x; 1.1837x over previous
#include <cuda_runtime.h>
#include <cuda_bf16.h>
#include <cstdint>
#include <math.h>

#define BATCH 2
#define SEQ   2048
#define DIM   4096
#define NH    32
#define NKV   8
#define HD    128
#define NREP  4
#define MTOT  (BATCH*SEQ)   // 4096
#define NQ    (NH*HD)       // 4096
#define NKVD  (NKV*HD)      // 1024
#define NQKV  (NQ + 2*NKVD) // 6144

// -------- scratch (device globals) --------
__device__ float g_qkv[(size_t)MTOT*NQKV];          // fused projection output

__device__ __nv_bfloat16 g_xh[(size_t)MTOT*DIM],   g_xl[(size_t)MTOT*DIM];
__device__ __nv_bfloat16 g_wqkvTh[(size_t)NQKV*DIM], g_wqkvTl[(size_t)NQKV*DIM];
__device__ __nv_bfloat16 g_woTh[(size_t)DIM*NQ],   g_woTl[(size_t)DIM*NQ];
__device__ __nv_bfloat16 g_aoh[(size_t)MTOT*NQ],   g_aol[(size_t)MTOT*NQ];
__device__ __nv_bfloat16 g_qh[(size_t)MTOT*NQ],    g_ql[(size_t)MTOT*NQ];
__device__ __nv_bfloat16 g_kh[(size_t)MTOT*NKVD],  g_kl[(size_t)MTOT*NKVD];
__device__ __nv_bfloat16 g_vh[(size_t)MTOT*NKVD],  g_vl[(size_t)MTOT*NKVD];

// ============================================================
// PTX helpers
// ============================================================
__device__ __forceinline__ uint32_t smem_u32(const void* p) {
    uint32_t a;
    asm("{ .reg .u64 t; cvta.to.shared.u64 t, %1; cvt.u32.u64 %0, t; }" : "=r"(a) : "l"(p));
    return a;
}
__device__ __forceinline__ void cp16(uint32_t dst, const void* src) {
    asm volatile("cp.async.cg.shared.global [%0], [%1], 16;" :: "r"(dst), "l"(src));
}
#define CP_COMMIT()  asm volatile("cp.async.commit_group;")
#define CP_WAIT1()   asm volatile("cp.async.wait_group 1;")

__device__ __forceinline__ void ldsm4(uint32_t* r, uint32_t addr) {
    asm volatile("ldmatrix.sync.aligned.m8n8.x4.shared.b16 {%0,%1,%2,%3}, [%4];"
        : "=r"(r[0]), "=r"(r[1]), "=r"(r[2]), "=r"(r[3]) : "r"(addr));
}
__device__ __forceinline__ void ldsm4t(uint32_t* r, uint32_t addr) {
    asm volatile("ldmatrix.sync.aligned.m8n8.x4.trans.shared.b16 {%0,%1,%2,%3}, [%4];"
        : "=r"(r[0]), "=r"(r[1]), "=r"(r[2]), "=r"(r[3]) : "r"(addr));
}
__device__ __forceinline__ void mma16816(float* c, const uint32_t* a, const uint32_t* b) {
    asm volatile("mma.sync.aligned.m16n8k16.row.col.f32.bf16.bf16.f32 "
        "{%0,%1,%2,%3}, {%4,%5,%6,%7}, {%8,%9}, {%0,%1,%2,%3};"
        : "+f"(c[0]), "+f"(c[1]), "+f"(c[2]), "+f"(c[3])
        : "r"(a[0]), "r"(a[1]), "r"(a[2]), "r"(a[3]), "r"(b[0]), "r"(b[1]));
}
__device__ __forceinline__ uint32_t packbf(float a, float b) {
    __nv_bfloat162 v = __floats2bfloat162_rn(a, b);
    return *(uint32_t*)&v;
}

// swizzles
__device__ __forceinline__ uint32_t swz(int row, int seg) {     // 64B rows, 4 segs
    return (uint32_t)row * 64u + ((uint32_t)(seg ^ ((row >> 1) & 3)) << 4);
}
__device__ __forceinline__ uint32_t sw256(int row, int boff) {
    return (uint32_t)row * 256u + (uint32_t)(boff ^ ((row & 7) << 4));
}
__device__ __forceinline__ uint32_t sw128(int row, int boff) {
    return (uint32_t)row * 128u + (uint32_t)(boff ^ ((row & 7) << 4));
}

// ============================================================
// split-bf16 GEMM v4: CTA 128x128, BK=32, 512 threads (16 warps 4x4),
// warp tile 32x32 -> 4 warps/SMSP for latency hiding.
// 2-stage cp.async pipeline (v1 structure).
// ============================================================
#define BM 128
#define BN 128
#define BK 32
#define GOFF_AH 0u
#define GOFF_AL 8192u
#define GOFF_BH 16384u
#define GOFF_BL 24576u
#define GSTAGE  32768u
#define GEMM_SMEM (2*32768)

__global__ void __launch_bounds__(512, 1) gemm_mma(
    const __nv_bfloat16* __restrict__ Ah, const __nv_bfloat16* __restrict__ Al,
    const __nv_bfloat16* __restrict__ Bh, const __nv_bfloat16* __restrict__ Bl,
    float* __restrict__ C, int M, int N, int K)
{
    extern __shared__ char smem[];
    const uint32_t sb = smem_u32(smem);
    const int t = threadIdx.x;
    const int lane = t & 31, wid = t >> 5;
    const int m0 = blockIdx.y * BM, n0 = blockIdx.x * BN;

    // ---- loader: thread t -> row t>>2 (0..127), seg t&3; 1 cp16 per tile ----
    const int lrow = t >> 2, lseg = t & 3;
    const __nv_bfloat16* gAh = Ah + (size_t)(m0 + lrow) * K + lseg * 8;
    const __nv_bfloat16* gAl = Al + (size_t)(m0 + lrow) * K + lseg * 8;
    const __nv_bfloat16* gBh = Bh + (size_t)(n0 + lrow) * K + lseg * 8;
    const __nv_bfloat16* gBl = Bl + (size_t)(n0 + lrow) * K + lseg * 8;
    const uint32_t loff = swz(lrow, lseg);

#define LOAD_CHUNK(k0, base) do {                   \
    cp16((base) + GOFF_AH + loff, gAh + (k0));      \
    cp16((base) + GOFF_AL + loff, gAl + (k0));      \
    cp16((base) + GOFF_BH + loff, gBh + (k0));      \
    cp16((base) + GOFF_BL + loff, gBl + (k0));      \
} while (0)

    // ---- compute mapping: warp grid 4(M) x 4(N), warp tile 32x32 ----
    const int wm = (wid & 3) * 32;
    const int wn = (wid >> 2) * 32;
    const int arow = wm + (lane & 7) + ((lane >> 3) & 1) * 8;
    const int aseg = lane >> 4;                   // 0/1
    const int brow = wn + (lane & 7) + ((lane >> 4) & 1) * 8;
    const int bseg = (lane >> 3) & 1;             // 0/1

    float acc[2][4][4];
    #pragma unroll
    for (int i = 0; i < 2; i++)
        #pragma unroll
        for (int j = 0; j < 4; j++)
            #pragma unroll
            for (int v = 0; v < 4; v++) acc[i][j][v] = 0.f;

    const int nch = K / BK;                       // 128
    LOAD_CHUNK(0, sb);            CP_COMMIT();
    LOAD_CHUNK(BK, sb + GSTAGE);  CP_COMMIT();

    for (int ch = 0; ch < nch; ch++) {
        CP_WAIT1();
        __syncthreads();
        const uint32_t base = sb + (uint32_t)(ch & 1) * GSTAGE;

        #pragma unroll
        for (int ks = 0; ks < 2; ks++) {
            uint32_t ah[2][4], al[2][4], bh[2][4], bl[2][4];
            #pragma unroll
            for (int mt = 0; mt < 2; mt++) {
                uint32_t off = swz(arow + mt * 16, ks * 2 + aseg);
                ldsm4(ah[mt], base + GOFF_AH + off);
                ldsm4(al[mt], base + GOFF_AL + off);
            }
            #pragma unroll
            for (int np = 0; np < 2; np++) {
                uint32_t off = swz(brow + np * 16, ks * 2 + bseg);
                ldsm4(bh[np], base + GOFF_BH + off);
                ldsm4(bl[np], base + GOFF_BL + off);
            }
            #pragma unroll
            for (int np = 0; np < 2; np++)
                #pragma unroll
                for (int mt = 0; mt < 2; mt++) {
                    mma16816(acc[mt][np * 2],     ah[mt], bh[np] + 0);
                    mma16816(acc[mt][np * 2],     ah[mt], bl[np] + 0);
                    mma16816(acc[mt][np * 2],     al[mt], bh[np] + 0);
                    mma16816(acc[mt][np * 2 + 1], ah[mt], bh[np] + 2);
                    mma16816(acc[mt][np * 2 + 1], ah[mt], bl[np] + 2);
                    mma16816(acc[mt][np * 2 + 1], al[mt], bh[np] + 2);
                }
        }
        __syncthreads();
        if (ch + 2 < nch) LOAD_CHUNK((ch + 2) * BK, base);
        CP_COMMIT();
    }

    // ---- epilogue ----
    #pragma unroll
    for (int mt = 0; mt < 2; mt++) {
        int r0 = m0 + wm + mt * 16 + (lane >> 2);
        #pragma unroll
        for (int nt = 0; nt < 4; nt++) {
            int c0 = n0 + wn + nt * 8 + (lane & 3) * 2;
            *(float2*)(C + (size_t)r0 * N + c0)       = make_float2(acc[mt][nt][0], acc[mt][nt][1]);
            *(float2*)(C + (size_t)(r0 + 8) * N + c0) = make_float2(acc[mt][nt][2], acc[mt][nt][3]);
        }
    }
#undef LOAD_CHUNK
}

// ============================================================
// conversions
// ============================================================
__global__ void split2(const float* __restrict__ src, __nv_bfloat16* __restrict__ hi,
                       __nv_bfloat16* __restrict__ lo, int n2)
{
    int i = blockIdx.x * blockDim.x + threadIdx.x;
    if (i < n2) {
        float2 v = ((const float2*)src)[i];
        __nv_bfloat16 hx = __float2bfloat16(v.x), hy = __float2bfloat16(v.y);
        float rx = v.x - __bfloat162float(hx);
        float ry = v.y - __bfloat162float(hy);
        ((__nv_bfloat162*)hi)[i] = __halves2bfloat162(hx, hy);
        ((__nv_bfloat162*)lo)[i] = __halves2bfloat162(__float2bfloat16(rx), __float2bfloat16(ry));
    }
}

// merged transpose+split of wq/wk/wv into one [NQKV, DIM] buffer
// grid (192, 128), block (32,8)
__global__ void transpose_qkv(const float* __restrict__ Wq, const float* __restrict__ Wk,
                              const float* __restrict__ Wv,
                              __nv_bfloat16* __restrict__ Th, __nv_bfloat16* __restrict__ Tl)
{
    __shared__ float tile[32][33];
    int tx = threadIdx.x, ty = threadIdx.y;
    int bx = blockIdx.x;
    const float* src;
    int srcN, nsrc, rowoff;
    if (bx < 128)      { src = Wq; srcN = NQ;   nsrc = bx * 32;         rowoff = 0;    }
    else if (bx < 160) { src = Wk; srcN = NKVD; nsrc = (bx - 128) * 32; rowoff = NQ;   }
    else               { src = Wv; srcN = NKVD; nsrc = (bx - 160) * 32; rowoff = NQ + NKVD; }

    int n = nsrc + tx;
    #pragma unroll
    for (int j = 0; j < 4; j++) {
        int k = blockIdx.y * 32 + ty + j * 8;
        tile[ty + j * 8][tx] = src[(size_t)k * srcN + n];
    }
    __syncthreads();
    int k2 = blockIdx.y * 32 + tx;
    #pragma unroll
    for (int j = 0; j < 4; j++) {
        int n2 = rowoff + nsrc + ty + j * 8;
        float v = tile[tx][ty + j * 8];
        __nv_bfloat16 h = __float2bfloat16(v);
        Th[(size_t)n2 * DIM + k2] = h;
        Tl[(size_t)n2 * DIM + k2] = __float2bfloat16(v - __bfloat162float(h));
    }
}

__global__ void transpose_split(const float* __restrict__ W, __nv_bfloat16* __restrict__ Th,
                                __nv_bfloat16* __restrict__ Tl, int K, int N)
{
    __shared__ float tile[32][33];
    int tx = threadIdx.x, ty = threadIdx.y;
    int n = blockIdx.x * 32 + tx;
    #pragma unroll
    for (int j = 0; j < 4; j++) {
        int k = blockIdx.y * 32 + ty + j * 8;
        tile[ty + j * 8][tx] = W[(size_t)k * N + n];
    }
    __syncthreads();
    int k2 = blockIdx.y * 32 + tx;
    #pragma unroll
    for (int j = 0; j < 4; j++) {
        int n2 = blockIdx.x * 32 + ty + j * 8;
        float v = tile[tx][ty + j * 8];
        __nv_bfloat16 h = __float2bfloat16(v);
        Th[(size_t)n2 * K + k2] = h;
        Tl[(size_t)n2 * K + k2] = __float2bfloat16(v - __bfloat162float(h));
    }
}

// ============================================================
// rope + layout change + hi/lo split (reads fused qkv buffer, stride NQKV)
// ============================================================
__global__ void rope_split(const float* __restrict__ qkv,
                           const float* __restrict__ cos_, const float* __restrict__ sin_,
                           __nv_bfloat16* qh, __nv_bfloat16* ql,
                           __nv_bfloat16* kh, __nv_bfloat16* kl,
                           __nv_bfloat16* vh, __nv_bfloat16* vl)
{
    const int HD2 = HD / 2;
    const int nqp = BATCH * SEQ * NH * HD2;
    const int nkp = BATCH * SEQ * NKV * HD2;
    const float qscale = 0.08838834764831845f;
    int idx = blockIdx.x * blockDim.x + threadIdx.x;
    if (idx < nqp) {
        int i = idx % HD2;
        int h = (idx / HD2) % NH;
        int s = (idx / (HD2 * NH)) % SEQ;
        int b = idx / (HD2 * NH * SEQ);
        float2 x = *(const float2*)(qkv + (size_t)(b * SEQ + s) * NQKV + h * HD + 2 * i);
        float c = cos_[s * HD2 + i], sn = sin_[s * HD2 + i];
        float outr = (x.x * c - x.y * sn) * qscale;
        float outi = (x.x * sn + x.y * c) * qscale;
        __nv_bfloat16 hr = __float2bfloat16(outr), hi2 = __float2bfloat16(outi);
        size_t o = ((size_t)(b * NH + h) * SEQ + s) * HD + 2 * i;
        *(__nv_bfloat162*)(qh + o) = __halves2bfloat162(hr, hi2);
        *(__nv_bfloat162*)(ql + o) = __halves2bfloat162(
            __float2bfloat16(outr - __bfloat162float(hr)),
            __float2bfloat16(outi - __bfloat162float(hi2)));
    } else if (idx < nqp + 2 * nkp) {
        int j = idx - nqp;
        int isv = j >= nkp;
        if (isv) j -= nkp;
        int i = j % HD2;
        int h = (j / HD2) % NKV;
        int s = (j / (HD2 * NKV)) % SEQ;
        int b = j / (HD2 * NKV * SEQ);
        int coloff = isv ? (NQ + NKVD) : NQ;
        float2 x = *(const float2*)(qkv + (size_t)(b * SEQ + s) * NQKV + coloff + h * HD + 2 * i);
        float outr, outi;
        if (isv) { outr = x.x; outi = x.y; }
        else {
            float c = cos_[s * HD2 + i], sn = sin_[s * HD2 + i];
            outr = x.x * c - x.y * sn;
            outi = x.x * sn + x.y * c;
        }
        __nv_bfloat16 hr = __float2bfloat16(outr), hi2 = __float2bfloat16(outi);
        size_t o = ((size_t)(b * NKV + h) * SEQ + s) * HD + 2 * i;
        __nv_bfloat16* dh = isv ? vh : kh;
        __nv_bfloat16* dl = isv ? vl : kl;
        *(__nv_bfloat162*)(dh + o) = __halves2bfloat162(hr, hi2);
        *(__nv_bfloat162*)(dl + o) = __halves2bfloat162(
            __float2bfloat16(outr - __bfloat162float(hr)),
            __float2bfloat16(outi - __bfloat162float(hi2)));
    }
}

// ============================================================
// flash attention, mma.sync split-bf16 (byte-identical to R4)
// ============================================================
#define NTILE (SEQ/64)
#define KVSTG 65536u
#define QOFF  (3u*KVSTG)
#define PH_OFF QOFF
#define PL_OFF (QOFF + 8192u)
#define RED_OFF (QOFF + 16384u)
#define ATT_SMEM (QOFF + 32768u)

__global__ void __launch_bounds__(256) attn_mma(
    const __nv_bfloat16* __restrict__ qh, const __nv_bfloat16* __restrict__ ql,
    const __nv_bfloat16* __restrict__ kh, const __nv_bfloat16* __restrict__ kl,
    const __nv_bfloat16* __restrict__ vh, const __nv_bfloat16* __restrict__ vl,
    __nv_bfloat16* __restrict__ outh, __nv_bfloat16* __restrict__ outl)
{
    extern __shared__ char sm[];
    const uint32_t sb = smem_u32(sm);
    const int t = threadIdx.x, lane = t & 31, w = t >> 5;
    const int wm = w & 3, wn = w >> 2;
    const int qt = blockIdx.x, h = blockIdx.y, b = blockIdx.z;
    const int kvh = h >> 2;

    const __nv_bfloat16* qhg = qh + ((size_t)(b * NH + h) * SEQ + qt * 64) * HD;
    const __nv_bfloat16* qlg = ql + ((size_t)(b * NH + h) * SEQ + qt * 64) * HD;
    const size_t kvb = (size_t)(b * NKV + kvh) * SEQ * HD;

    {
        int r = t >> 2, seg = t & 3;
        #pragma unroll
        for (int j = 0; j < 4; j++) {
            int boff = seg * 64 + j * 16;
            uint4 a = *(const uint4*)(qhg + (size_t)r * HD + boff / 2);
            *(uint4*)(sm + QOFF + sw256(r, boff)) = a;
            uint4 c = *(const uint4*)(qlg + (size_t)r * HD + boff / 2);
            *(uint4*)(sm + QOFF + 16384u + sw256(r, boff)) = c;
        }
    }

    const int lrow = t >> 2, lseg = t & 3;
#define LOAD_KV(kt, stg) do {                                                   \
    uint32_t bufb = sb + (uint32_t)(stg) * KVSTG;                               \
    size_t grow = kvb + ((size_t)(kt) * 64 + lrow) * HD;                        \
    _Pragma("unroll")                                                           \
    for (int j = 0; j < 4; j++) {                                               \
        int boff = lseg * 64 + j * 16;                                          \
        uint32_t sd = sw256(lrow, boff);                                        \
        cp16(bufb + sd,          kh + grow + boff / 2);                         \
        cp16(bufb + 16384u + sd, kl + grow + boff / 2);                         \
        cp16(bufb + 32768u + sd, vh + grow + boff / 2);                         \
        cp16(bufb + 49152u + sd, vl + grow + boff / 2);                         \
    }                                                                           \
} while (0)

    LOAD_KV(0, 0); CP_COMMIT();
    LOAD_KV(1, 1); CP_COMMIT();
    __syncthreads();

    uint32_t qfh[8][4], qfl[8][4];
    {
        int ar = wm * 16 + (lane & 7) + ((lane >> 3) & 1) * 8;
        int ab = (lane >> 4) * 16;
        #pragma unroll
        for (int ks = 0; ks < 8; ks++) {
            ldsm4(qfh[ks], sb + QOFF + sw256(ar, ks * 32 + ab));
            ldsm4(qfl[ks], sb + QOFF + 16384u + sw256(ar, ks * 32 + ab));
        }
    }

    float m[2] = {-1e30f, -1e30f}, l[2] = {0.f, 0.f};
    float oacc[8][4];
    #pragma unroll
    for (int i = 0; i < 8; i++)
        #pragma unroll
        for (int j = 0; j < 4; j++) oacc[i][j] = 0.f;

    float* redm = (float*)(sm + RED_OFF);
    float* reds = redm + 128;
    const int row1 = wm * 16 + (lane >> 2);
    const int row2 = row1 + 8;

    for (int kt = 0; kt < NTILE; kt++) {
        CP_WAIT1();
        __syncthreads();
        const uint32_t kbuf = sb + (uint32_t)(kt % 3) * KVSTG;
        const uint32_t vbuf = kbuf + 32768u;

        float sacc[4][4];
        #pragma unroll
        for (int i = 0; i < 4; i++)
            #pragma unroll
            for (int j = 0; j < 4; j++) sacc[i][j] = 0.f;
        {
            int br = wn * 32 + (lane & 7) + (lane >> 4) * 8;
            int bb0 = ((lane >> 3) & 1) * 16;
            #pragma unroll
            for (int ks = 0; ks < 8; ks++) {
                #pragma unroll
                for (int np = 0; np < 2; np++) {
                    uint32_t bh[4], bl[4];
                    uint32_t off = sw256(br + np * 16, ks * 32 + bb0);
                    ldsm4(bh, kbuf + off);
                    ldsm4(bl, kbuf + 16384u + off);
                    mma16816(sacc[np * 2],     qfh[ks], bh + 0);
                    mma16816(sacc[np * 2],     qfh[ks], bl + 0);
                    mma16816(sacc[np * 2],     qfl[ks], bh + 0);
                    mma16816(sacc[np * 2 + 1], qfh[ks], bh + 2);
                    mma16816(sacc[np * 2 + 1], qfh[ks], bl + 2);
                    mma16816(sacc[np * 2 + 1], qfl[ks], bh + 2);
                }
            }
        }

        float mx1 = -1e30f, mx2 = -1e30f;
        #pragma unroll
        for (int nt = 0; nt < 4; nt++) {
            mx1 = fmaxf(mx1, fmaxf(sacc[nt][0], sacc[nt][1]));
            mx2 = fmaxf(mx2, fmaxf(sacc[nt][2], sacc[nt][3]));
        }
        mx1 = fmaxf(mx1, __shfl_xor_sync(0xffffffffu, mx1, 1));
        mx1 = fmaxf(mx1, __shfl_xor_sync(0xffffffffu, mx1, 2));
        mx2 = fmaxf(mx2, __shfl_xor_sync(0xffffffffu, mx2, 1));
        mx2 = fmaxf(mx2, __shfl_xor_sync(0xffffffffu, mx2, 2));
        if ((lane & 3) == 0) {
            redm[wn * 64 + row1] = mx1;
            redm[wn * 64 + row2] = mx2;
        }
        __syncthreads();
        if (kt + 2 < NTILE) LOAD_KV(kt + 2, (kt + 2) % 3);
        CP_COMMIT();

        float mn1 = fmaxf(m[0], fmaxf(redm[row1], redm[64 + row1]));
        float mn2 = fmaxf(m[1], fmaxf(redm[row2], redm[64 + row2]));
        float al1 = __expf(m[0] - mn1), al2 = __expf(m[1] - mn2);
        float p[4][4], s1 = 0.f, s2 = 0.f;
        #pragma unroll
        for (int nt = 0; nt < 4; nt++) {
            p[nt][0] = __expf(sacc[nt][0] - mn1);
            p[nt][1] = __expf(sacc[nt][1] - mn1);
            p[nt][2] = __expf(sacc[nt][2] - mn2);
            p[nt][3] = __expf(sacc[nt][3] - mn2);
            s1 += p[nt][0] + p[nt][1];
            s2 += p[nt][2] + p[nt][3];
        }
        s1 += __shfl_xor_sync(0xffffffffu, s1, 1);
        s1 += __shfl_xor_sync(0xffffffffu, s1, 2);
        s2 += __shfl_xor_sync(0xffffffffu, s2, 1);
        s2 += __shfl_xor_sync(0xffffffffu, s2, 2);
        if ((lane & 3) == 0) {
            reds[wn * 64 + row1] = s1;
            reds[wn * 64 + row2] = s2;
        }
        {
            int cb = wn * 64 + (lane & 3) * 4;
            #pragma unroll
            for (int nt = 0; nt < 4; nt++) {
                float h0 = p[nt][0], h1 = p[nt][1], h2 = p[nt][2], h3 = p[nt][3];
                uint32_t ph01 = packbf(h0, h1), ph23 = packbf(h2, h3);
                __nv_bfloat162 b01 = *(__nv_bfloat162*)&ph01;
                __nv_bfloat162 b23 = *(__nv_bfloat162*)&ph23;
                uint32_t pl01 = packbf(h0 - __bfloat162float(b01.x), h1 - __bfloat162float(b01.y));
                uint32_t pl23 = packbf(h2 - __bfloat162float(b23.x), h3 - __bfloat162float(b23.y));
                uint32_t o1 = sw128(row1, cb + nt * 16);
                uint32_t o2 = sw128(row2, cb + nt * 16);
                *(uint32_t*)(sm + PH_OFF + o1) = ph01;
                *(uint32_t*)(sm + PH_OFF + o2) = ph23;
                *(uint32_t*)(sm + PL_OFF + o1) = pl01;
                *(uint32_t*)(sm + PL_OFF + o2) = pl23;
            }
        }
        __syncthreads();
        {
            float tot1 = reds[row1] + reds[64 + row1];
            float tot2 = reds[row2] + reds[64 + row2];
            l[0] = l[0] * al1 + tot1;
            l[1] = l[1] * al2 + tot2;
            m[0] = mn1; m[1] = mn2;
            #pragma unroll
            for (int nt = 0; nt < 8; nt++) {
                oacc[nt][0] *= al1; oacc[nt][1] *= al1;
                oacc[nt][2] *= al2; oacc[nt][3] *= al2;
            }
        }

        {
            int par = wm * 16 + (lane & 7) + ((lane >> 3) & 1) * 8;
            int pab = (lane >> 4) * 16;
            int vr0 = (lane & 7) + ((lane >> 3) & 1) * 8;
            int vb0 = wn * 128 + (lane >> 4) * 16;
            #pragma unroll
            for (int ks = 0; ks < 4; ks++) {
                uint32_t pfh[4], pfl[4];
                ldsm4(pfh, sb + PH_OFF + sw128(par, ks * 32 + pab));
                ldsm4(pfl, sb + PL_OFF + sw128(par, ks * 32 + pab));
                #pragma unroll
                for (int np = 0; np < 4; np++) {
                    uint32_t wh[4], wl[4];
                    uint32_t off = sw256(ks * 16 + vr0, vb0 + np * 32);
                    ldsm4t(wh, vbuf + off);
                    ldsm4t(wl, vbuf + 16384u + off);
                    mma16816(oacc[np * 2],     pfh, wh + 0);
                    mma16816(oacc[np * 2],     pfh, wl + 0);
                    mma16816(oacc[np * 2],     pfl, wh + 0);
                    mma16816(oacc[np * 2 + 1], pfh, wh + 2);
                    mma16816(oacc[np * 2 + 1], pfh, wl + 2);
                    mma16816(oacc[np * 2 + 1], pfl, wh + 2);
                }
            }
        }
        __syncthreads();
    }

    {
        float inv1 = 1.f / l[0], inv2 = 1.f / l[1];
        int rg1 = qt * 64 + row1, rg2 = qt * 64 + row2;
        size_t b1 = ((size_t)(b * SEQ + rg1) * NH + h) * HD;
        size_t b2 = ((size_t)(b * SEQ + rg2) * NH + h) * HD;
        #pragma unroll
        for (int nt = 0; nt < 8; nt++) {
            int c0 = wn * 64 + nt * 8 + (lane & 3) * 2;
            float f0 = oacc[nt][0] * inv1, f1 = oacc[nt][1] * inv1;
            float f2 = oacc[nt][2] * inv2, f3 = oacc[nt][3] * inv2;
            uint32_t h01 = packbf(f0, f1), h23 = packbf(f2, f3);
            __nv_bfloat162 bb01 = *(__nv_bfloat162*)&h01;
            __nv_bfloat162 bb23 = *(__nv_bfloat162*)&h23;
            uint32_t l01 = packbf(f0 - __bfloat162float(bb01.x), f1 - __bfloat162float(bb01.y));
            uint32_t l23 = packbf(f2 - __bfloat162float(bb23.x), f3 - __bfloat162float(bb23.y));
            *(uint32_t*)(outh + b1 + c0) = h01;
            *(uint32_t*)(outh + b2 + c0) = h23;
            *(uint32_t*)(outl + b1 + c0) = l01;
            *(uint32_t*)(outl + b2 + c0) = l23;
        }
    }
#undef LOAD_KV
}

// ============================================================
// launch  (gemm_qkv at launch index 3 for the ncu capture slot)
// ============================================================
extern "C" void kernel_launch(void* const* d_in, const int* in_sizes, int n_in,
                              void* d_out, int out_size)
{
    const float* x  = (const float*)d_in[0];
    const float* wq = (const float*)d_in[1];
    const float* wk = (const float*)d_in[2];
    const float* wv = (const float*)d_in[3];
    const float* wo = (const float*)d_in[4];
    const float* fcos = (const float*)d_in[7];
    const float* fsin = (const float*)d_in[8];
    float* out = (float*)d_out;

    float* gqkv;
    __nv_bfloat16 *xh, *xl, *wqkvTh, *wqkvTl, *woTh, *woTl;
    __nv_bfloat16 *aoh, *aol, *pqh, *pql, *pkh, *pkl, *pvh, *pvl;
    cudaGetSymbolAddress((void**)&gqkv, g_qkv);
    cudaGetSymbolAddress((void**)&xh, g_xh);         cudaGetSymbolAddress((void**)&xl, g_xl);
    cudaGetSymbolAddress((void**)&wqkvTh, g_wqkvTh); cudaGetSymbolAddress((void**)&wqkvTl, g_wqkvTl);
    cudaGetSymbolAddress((void**)&woTh, g_woTh);     cudaGetSymbolAddress((void**)&woTl, g_woTl);
    cudaGetSymbolAddress((void**)&aoh, g_aoh);       cudaGetSymbolAddress((void**)&aol, g_aol);
    cudaGetSymbolAddress((void**)&pqh, g_qh);        cudaGetSymbolAddress((void**)&pql, g_ql);
    cudaGetSymbolAddress((void**)&pkh, g_kh);        cudaGetSymbolAddress((void**)&pkl, g_kl);
    cudaGetSymbolAddress((void**)&pvh, g_vh);        cudaGetSymbolAddress((void**)&pvl, g_vl);

    cudaFuncSetAttribute(gemm_mma, cudaFuncAttributeMaxDynamicSharedMemorySize, GEMM_SMEM);
    cudaFuncSetAttribute(attn_mma, cudaFuncAttributeMaxDynamicSharedMemorySize, ATT_SMEM);

    // 0: split x
    {
        int n2 = (int)((size_t)MTOT * DIM / 2);
        split2<<<(n2 + 255) / 256, 256>>>(x, xh, xl, n2);
    }
    // 1: merged qkv weight transpose, 2: wo transpose
    transpose_qkv<<<dim3(192, DIM / 32), dim3(32, 8)>>>(wq, wk, wv, wqkvTh, wqkvTl);
    transpose_split<<<dim3(DIM / 32, NQ / 32), dim3(32, 8)>>>(wo, woTh, woTl, NQ, DIM);
    // 3: fused qkv projection  <-- ncu capture slot
    gemm_mma<<<dim3(NQKV / BN, MTOT / BM), 512, GEMM_SMEM>>>(xh, xl, wqkvTh, wqkvTl,
                                                             gqkv, MTOT, NQKV, DIM);
    // 4: rope + split + relayout
    {
        int total = BATCH * SEQ * (NH + 2 * NKV) * (HD / 2);
        rope_split<<<(total + 255) / 256, 256>>>(gqkv, fcos, fsin,
                                                 pqh, pql, pkh, pkl, pvh, pvl);
    }
    // 5: attention
    {
        dim3 grid(SEQ / 64, NH, BATCH);
        attn_mma<<<grid, 256, ATT_SMEM>>>(pqh, pql, pkh, pkl, pvh, pvl, aoh, aol);
    }
    // 6: output projection
    gemm_mma<<<dim3(DIM / BN, MTOT / BM), 512, GEMM_SMEM>>>(aoh, aol, woTh, woTl, out, MTOT, DIM, NQ);
}

// round 8
// speedup vs baseline: 1.4802x; 1.1111x over previous
#include <cuda_runtime.h>
#include <cuda_bf16.h>
#include <cstdint>
#include <math.h>

#define BATCH 2
#define SEQ   2048
#define DIM   4096
#define NH    32
#define NKV   8
#define HD    128
#define NREP  4
#define MTOT  (BATCH*SEQ)   // 4096
#define NQ    (NH*HD)       // 4096
#define NKVD  (NKV*HD)      // 1024
#define NQKV  (NQ + 2*NKVD) // 6144

// -------- scratch (device globals) --------
__device__ float g_qkv[(size_t)MTOT*NQKV];

__device__ __nv_bfloat16 g_xh[(size_t)MTOT*DIM],   g_xl[(size_t)MTOT*DIM];
__device__ __nv_bfloat16 g_wqkvTh[(size_t)NQKV*DIM], g_wqkvTl[(size_t)NQKV*DIM];
__device__ __nv_bfloat16 g_woTh[(size_t)DIM*NQ],   g_woTl[(size_t)DIM*NQ];
__device__ __nv_bfloat16 g_aoh[(size_t)MTOT*NQ],   g_aol[(size_t)MTOT*NQ];
__device__ __nv_bfloat16 g_qh[(size_t)MTOT*NQ],    g_ql[(size_t)MTOT*NQ];
__device__ __nv_bfloat16 g_kh[(size_t)MTOT*NKVD],  g_kl[(size_t)MTOT*NKVD];
__device__ __nv_bfloat16 g_vh[(size_t)MTOT*NKVD],  g_vl[(size_t)MTOT*NKVD];

// ============================================================
// PTX helpers
// ============================================================
__device__ __forceinline__ uint32_t smem_u32(const void* p) {
    uint32_t a;
    asm("{ .reg .u64 t; cvta.to.shared.u64 t, %1; cvt.u32.u64 %0, t; }" : "=r"(a) : "l"(p));
    return a;
}
__device__ __forceinline__ void cp16(uint32_t dst, const void* src) {
    asm volatile("cp.async.cg.shared.global [%0], [%1], 16;" :: "r"(dst), "l"(src));
}
#define CP_COMMIT()  asm volatile("cp.async.commit_group;")
#define CP_WAIT1()   asm volatile("cp.async.wait_group 1;")
#define CP_WAIT0()   asm volatile("cp.async.wait_group 0;")

__device__ __forceinline__ void ldsm4(uint32_t* r, uint32_t addr) {
    asm volatile("ldmatrix.sync.aligned.m8n8.x4.shared.b16 {%0,%1,%2,%3}, [%4];"
        : "=r"(r[0]), "=r"(r[1]), "=r"(r[2]), "=r"(r[3]) : "r"(addr));
}
__device__ __forceinline__ void ldsm4t(uint32_t* r, uint32_t addr) {
    asm volatile("ldmatrix.sync.aligned.m8n8.x4.trans.shared.b16 {%0,%1,%2,%3}, [%4];"
        : "=r"(r[0]), "=r"(r[1]), "=r"(r[2]), "=r"(r[3]) : "r"(addr));
}
__device__ __forceinline__ void mma16816(float* c, const uint32_t* a, const uint32_t* b) {
    asm volatile("mma.sync.aligned.m16n8k16.row.col.f32.bf16.bf16.f32 "
        "{%0,%1,%2,%3}, {%4,%5,%6,%7}, {%8,%9}, {%0,%1,%2,%3};"
        : "+f"(c[0]), "+f"(c[1]), "+f"(c[2]), "+f"(c[3])
        : "r"(a[0]), "r"(a[1]), "r"(a[2]), "r"(a[3]), "r"(b[0]), "r"(b[1]));
}
__device__ __forceinline__ uint32_t packbf(float a, float b) {
    __nv_bfloat162 v = __floats2bfloat162_rn(a, b);
    return *(uint32_t*)&v;
}

__device__ __forceinline__ uint32_t swz(int row, int seg) {     // 64B rows, 4 segs
    return (uint32_t)row * 64u + ((uint32_t)(seg ^ ((row >> 1) & 3)) << 4);
}
__device__ __forceinline__ uint32_t sw256(int row, int boff) {
    return (uint32_t)row * 256u + (uint32_t)(boff ^ ((row & 7) << 4));
}
__device__ __forceinline__ uint32_t sw128(int row, int boff) {
    return (uint32_t)row * 128u + (uint32_t)(boff ^ ((row & 7) << 4));
}

// ============================================================
// split-bf16 GEMM (R7 winner, unchanged): CTA 128x128, BK=32,
// 512 threads (16 warps 4x4), warp tile 32x32, 2-stage cp.async.
// ============================================================
#define BM 128
#define BN 128
#define BK 32
#define GOFF_AH 0u
#define GOFF_AL 8192u
#define GOFF_BH 16384u
#define GOFF_BL 24576u
#define GSTAGE  32768u
#define GEMM_SMEM (2*32768)

__global__ void __launch_bounds__(512, 1) gemm_mma(
    const __nv_bfloat16* __restrict__ Ah, const __nv_bfloat16* __restrict__ Al,
    const __nv_bfloat16* __restrict__ Bh, const __nv_bfloat16* __restrict__ Bl,
    float* __restrict__ C, int M, int N, int K)
{
    extern __shared__ char smem[];
    const uint32_t sb = smem_u32(smem);
    const int t = threadIdx.x;
    const int lane = t & 31, wid = t >> 5;
    const int m0 = blockIdx.y * BM, n0 = blockIdx.x * BN;

    const int lrow = t >> 2, lseg = t & 3;
    const __nv_bfloat16* gAh = Ah + (size_t)(m0 + lrow) * K + lseg * 8;
    const __nv_bfloat16* gAl = Al + (size_t)(m0 + lrow) * K + lseg * 8;
    const __nv_bfloat16* gBh = Bh + (size_t)(n0 + lrow) * K + lseg * 8;
    const __nv_bfloat16* gBl = Bl + (size_t)(n0 + lrow) * K + lseg * 8;
    const uint32_t loff = swz(lrow, lseg);

#define LOAD_CHUNK(k0, base) do {                   \
    cp16((base) + GOFF_AH + loff, gAh + (k0));      \
    cp16((base) + GOFF_AL + loff, gAl + (k0));      \
    cp16((base) + GOFF_BH + loff, gBh + (k0));      \
    cp16((base) + GOFF_BL + loff, gBl + (k0));      \
} while (0)

    const int wm = (wid & 3) * 32;
    const int wn = (wid >> 2) * 32;
    const int arow = wm + (lane & 7) + ((lane >> 3) & 1) * 8;
    const int aseg = lane >> 4;
    const int brow = wn + (lane & 7) + ((lane >> 4) & 1) * 8;
    const int bseg = (lane >> 3) & 1;

    float acc[2][4][4];
    #pragma unroll
    for (int i = 0; i < 2; i++)
        #pragma unroll
        for (int j = 0; j < 4; j++)
            #pragma unroll
            for (int v = 0; v < 4; v++) acc[i][j][v] = 0.f;

    const int nch = K / BK;
    LOAD_CHUNK(0, sb);            CP_COMMIT();
    LOAD_CHUNK(BK, sb + GSTAGE);  CP_COMMIT();

    for (int ch = 0; ch < nch; ch++) {
        CP_WAIT1();
        __syncthreads();
        const uint32_t base = sb + (uint32_t)(ch & 1) * GSTAGE;

        #pragma unroll
        for (int ks = 0; ks < 2; ks++) {
            uint32_t ah[2][4], al[2][4], bh[2][4], bl[2][4];
            #pragma unroll
            for (int mt = 0; mt < 2; mt++) {
                uint32_t off = swz(arow + mt * 16, ks * 2 + aseg);
                ldsm4(ah[mt], base + GOFF_AH + off);
                ldsm4(al[mt], base + GOFF_AL + off);
            }
            #pragma unroll
            for (int np = 0; np < 2; np++) {
                uint32_t off = swz(brow + np * 16, ks * 2 + bseg);
                ldsm4(bh[np], base + GOFF_BH + off);
                ldsm4(bl[np], base + GOFF_BL + off);
            }
            #pragma unroll
            for (int np = 0; np < 2; np++)
                #pragma unroll
                for (int mt = 0; mt < 2; mt++) {
                    mma16816(acc[mt][np * 2],     ah[mt], bh[np] + 0);
                    mma16816(acc[mt][np * 2],     ah[mt], bl[np] + 0);
                    mma16816(acc[mt][np * 2],     al[mt], bh[np] + 0);
                    mma16816(acc[mt][np * 2 + 1], ah[mt], bh[np] + 2);
                    mma16816(acc[mt][np * 2 + 1], ah[mt], bl[np] + 2);
                    mma16816(acc[mt][np * 2 + 1], al[mt], bh[np] + 2);
                }
        }
        __syncthreads();
        if (ch + 2 < nch) LOAD_CHUNK((ch + 2) * BK, base);
        CP_COMMIT();
    }

    #pragma unroll
    for (int mt = 0; mt < 2; mt++) {
        int r0 = m0 + wm + mt * 16 + (lane >> 2);
        #pragma unroll
        for (int nt = 0; nt < 4; nt++) {
            int c0 = n0 + wn + nt * 8 + (lane & 3) * 2;
            *(float2*)(C + (size_t)r0 * N + c0)       = make_float2(acc[mt][nt][0], acc[mt][nt][1]);
            *(float2*)(C + (size_t)(r0 + 8) * N + c0) = make_float2(acc[mt][nt][2], acc[mt][nt][3]);
        }
    }
#undef LOAD_CHUNK
}

// ============================================================
// prep: fused  (a) x hi/lo split  (b) wq/wk/wv transpose+split
//              (c) wo transpose+split   — one launch
// grid: [0,32768) split-x  [32768,57344) qkv-T  [57344,73728) wo-T
// block: 256 threads
// ============================================================
#define PREP_SPLIT_BLKS 32768
#define PREP_QKV_BLKS   24576
#define PREP_TOTAL      (PREP_SPLIT_BLKS + PREP_QKV_BLKS + 16384)

__global__ void __launch_bounds__(256) prep_kernel(
    const float* __restrict__ x,  const float* __restrict__ Wq,
    const float* __restrict__ Wk, const float* __restrict__ Wv,
    const float* __restrict__ Wo,
    __nv_bfloat16* __restrict__ xh,  __nv_bfloat16* __restrict__ xl,
    __nv_bfloat16* __restrict__ qkvTh, __nv_bfloat16* __restrict__ qkvTl,
    __nv_bfloat16* __restrict__ woTh,  __nv_bfloat16* __restrict__ woTl)
{
    __shared__ float tile[32][33];
    int bid = blockIdx.x, t = threadIdx.x;

    if (bid < PREP_SPLIT_BLKS) {
        int i = bid * 256 + t;                      // float2 index
        float2 v = ((const float2*)x)[i];
        __nv_bfloat16 hx = __float2bfloat16(v.x), hy = __float2bfloat16(v.y);
        ((__nv_bfloat162*)xh)[i] = __halves2bfloat162(hx, hy);
        ((__nv_bfloat162*)xl)[i] = __halves2bfloat162(
            __float2bfloat16(v.x - __bfloat162float(hx)),
            __float2bfloat16(v.y - __bfloat162float(hy)));
        return;
    }

    int tx = t & 31, ty = t >> 5;
    const float* src; __nv_bfloat16 *Th, *Tl;
    int srcN, outK, nsrc, rowoff, by;
    if (bid < PREP_SPLIT_BLKS + PREP_QKV_BLKS) {
        int b2 = bid - PREP_SPLIT_BLKS;
        int bx = b2 % 192; by = b2 / 192;
        Th = qkvTh; Tl = qkvTl; outK = DIM;
        if (bx < 128)      { src = Wq; srcN = NQ;   nsrc = bx * 32;         rowoff = 0;    }
        else if (bx < 160) { src = Wk; srcN = NKVD; nsrc = (bx - 128) * 32; rowoff = NQ;   }
        else               { src = Wv; srcN = NKVD; nsrc = (bx - 160) * 32; rowoff = NQ + NKVD; }
    } else {
        int b2 = bid - PREP_SPLIT_BLKS - PREP_QKV_BLKS;
        int bx = b2 % 128; by = b2 / 128;
        Th = woTh; Tl = woTl; outK = NQ;
        src = Wo; srcN = DIM; nsrc = bx * 32; rowoff = 0;
    }

    int n = nsrc + tx;
    #pragma unroll
    for (int j = 0; j < 4; j++) {
        int k = by * 32 + ty + j * 8;
        tile[ty + j * 8][tx] = src[(size_t)k * srcN + n];
    }
    __syncthreads();
    int k2 = by * 32 + tx;
    #pragma unroll
    for (int j = 0; j < 4; j++) {
        int n2 = rowoff + nsrc + ty + j * 8;
        float v = tile[tx][ty + j * 8];
        __nv_bfloat16 h = __float2bfloat16(v);
        Th[(size_t)n2 * outK + k2] = h;
        Tl[(size_t)n2 * outK + k2] = __float2bfloat16(v - __bfloat162float(h));
    }
}

// ============================================================
// rope + layout change + hi/lo split (reads fused qkv, stride NQKV)
// ============================================================
__global__ void rope_split(const float* __restrict__ qkv,
                           const float* __restrict__ cos_, const float* __restrict__ sin_,
                           __nv_bfloat16* qh, __nv_bfloat16* ql,
                           __nv_bfloat16* kh, __nv_bfloat16* kl,
                           __nv_bfloat16* vh, __nv_bfloat16* vl)
{
    const int HD2 = HD / 2;
    const int nqp = BATCH * SEQ * NH * HD2;
    const int nkp = BATCH * SEQ * NKV * HD2;
    const float qscale = 0.08838834764831845f;
    int idx = blockIdx.x * blockDim.x + threadIdx.x;
    if (idx < nqp) {
        int i = idx % HD2;
        int h = (idx / HD2) % NH;
        int s = (idx / (HD2 * NH)) % SEQ;
        int b = idx / (HD2 * NH * SEQ);
        float2 x = *(const float2*)(qkv + (size_t)(b * SEQ + s) * NQKV + h * HD + 2 * i);
        float c = cos_[s * HD2 + i], sn = sin_[s * HD2 + i];
        float outr = (x.x * c - x.y * sn) * qscale;
        float outi = (x.x * sn + x.y * c) * qscale;
        __nv_bfloat16 hr = __float2bfloat16(outr), hi2 = __float2bfloat16(outi);
        size_t o = ((size_t)(b * NH + h) * SEQ + s) * HD + 2 * i;
        *(__nv_bfloat162*)(qh + o) = __halves2bfloat162(hr, hi2);
        *(__nv_bfloat162*)(ql + o) = __halves2bfloat162(
            __float2bfloat16(outr - __bfloat162float(hr)),
            __float2bfloat16(outi - __bfloat162float(hi2)));
    } else if (idx < nqp + 2 * nkp) {
        int j = idx - nqp;
        int isv = j >= nkp;
        if (isv) j -= nkp;
        int i = j % HD2;
        int h = (j / HD2) % NKV;
        int s = (j / (HD2 * NKV)) % SEQ;
        int b = j / (HD2 * NKV * SEQ);
        int coloff = isv ? (NQ + NKVD) : NQ;
        float2 x = *(const float2*)(qkv + (size_t)(b * SEQ + s) * NQKV + coloff + h * HD + 2 * i);
        float outr, outi;
        if (isv) { outr = x.x; outi = x.y; }
        else {
            float c = cos_[s * HD2 + i], sn = sin_[s * HD2 + i];
            outr = x.x * c - x.y * sn;
            outi = x.x * sn + x.y * c;
        }
        __nv_bfloat16 hr = __float2bfloat16(outr), hi2 = __float2bfloat16(outi);
        size_t o = ((size_t)(b * NKV + h) * SEQ + s) * HD + 2 * i;
        __nv_bfloat16* dh = isv ? vh : kh;
        __nv_bfloat16* dl = isv ? vl : kl;
        *(__nv_bfloat162*)(dh + o) = __halves2bfloat162(hr, hi2);
        *(__nv_bfloat162*)(dl + o) = __halves2bfloat162(
            __float2bfloat16(outr - __bfloat162float(hr)),
            __float2bfloat16(outi - __bfloat162float(hi2)));
    }
}

// ============================================================
// flash attention v2: 512 threads, 128 q-rows/CTA (16 warps: 8 M x 2 halves),
// 2-stage KV ring, Q in smem (reloaded per tile).
// smem: KV 2x64KB | Qh 32KB | Ql 32KB | PH 16KB | PL 16KB | red 2KB = 226KB
// ============================================================
#define NTILE (SEQ/64)
#define AKV_STG 65536u
#define AQ_OFF  131072u
#define APH_OFF 196608u
#define APL_OFF 212992u
#define ARED_OFF 229376u
#define ATT_SMEM 231424

__global__ void __launch_bounds__(512, 1) attn_mma(
    const __nv_bfloat16* __restrict__ qh, const __nv_bfloat16* __restrict__ ql,
    const __nv_bfloat16* __restrict__ kh, const __nv_bfloat16* __restrict__ kl,
    const __nv_bfloat16* __restrict__ vh, const __nv_bfloat16* __restrict__ vl,
    __nv_bfloat16* __restrict__ outh, __nv_bfloat16* __restrict__ outl)
{
    extern __shared__ char sm[];
    const uint32_t sb = smem_u32(sm);
    const int t = threadIdx.x, lane = t & 31, w = t >> 5;
    const int wm = w & 7, wn = w >> 3;
    const int qt = blockIdx.x, h = blockIdx.y, b = blockIdx.z;
    const int kvh = h >> 2;

    const __nv_bfloat16* qhg = qh + ((size_t)(b * NH + h) * SEQ + qt * 128) * HD;
    const __nv_bfloat16* qlg = ql + ((size_t)(b * NH + h) * SEQ + qt * 128) * HD;
    const size_t kvb = (size_t)(b * NKV + kvh) * SEQ * HD;

    // ---- Q (128 rows) -> smem ----
    {
        int r = t >> 2, seg = t & 3;
        #pragma unroll
        for (int j = 0; j < 4; j++) {
            int boff = seg * 64 + j * 16;
            uint4 a = *(const uint4*)(qhg + (size_t)r * HD + boff / 2);
            *(uint4*)(sm + AQ_OFF + sw256(r, boff)) = a;
            uint4 c = *(const uint4*)(qlg + (size_t)r * HD + boff / 2);
            *(uint4*)(sm + AQ_OFF + 32768u + sw256(r, boff)) = c;
        }
    }

    // ---- KV loader: 512 threads, 64 rows x 256B x4 tiles per stage ----
    const int lrow = t >> 3, lsg = t & 7;
#define LOAD_KV(kt, stg) do {                                                   \
    uint32_t bufb = sb + (uint32_t)(stg) * AKV_STG;                             \
    size_t grow = kvb + ((size_t)(kt) * 64 + lrow) * HD;                        \
    _Pragma("unroll")                                                           \
    for (int j = 0; j < 2; j++) {                                               \
        int boff = lsg * 32 + j * 16;                                           \
        uint32_t sd = sw256(lrow, boff);                                        \
        cp16(bufb + sd,          kh + grow + boff / 2);                         \
        cp16(bufb + 16384u + sd, kl + grow + boff / 2);                         \
        cp16(bufb + 32768u + sd, vh + grow + boff / 2);                         \
        cp16(bufb + 49152u + sd, vl + grow + boff / 2);                         \
    }                                                                           \
} while (0)

    LOAD_KV(0, 0); CP_COMMIT();

    float m[2] = {-1e30f, -1e30f}, l[2] = {0.f, 0.f};
    float oacc[8][4];
    #pragma unroll
    for (int i = 0; i < 8; i++)
        #pragma unroll
        for (int j = 0; j < 4; j++) oacc[i][j] = 0.f;

    float* redm = (float*)(sm + ARED_OFF);      // [2][128]
    float* reds = redm + 256;                   // [2][128]
    const int row1 = wm * 16 + (lane >> 2);
    const int row2 = row1 + 8;

    // fragment index bases
    const int qar = wm * 16 + (lane & 7) + ((lane >> 3) & 1) * 8;
    const int qab = (lane >> 4) * 16;

    for (int kt = 0; kt < NTILE; kt++) {
        if (kt + 1 < NTILE) { LOAD_KV(kt + 1, (kt + 1) & 1); CP_COMMIT(); CP_WAIT1(); }
        else                { CP_WAIT0(); }
        __syncthreads();                                  // tile kt ready; Q ready (kt=0)
        const uint32_t kbuf = sb + (uint32_t)(kt & 1) * AKV_STG;
        const uint32_t vbuf = kbuf + 32768u;

        // ---- QK^T: 16 rows x 32 keys per warp ----
        float sacc[4][4];
        #pragma unroll
        for (int i = 0; i < 4; i++)
            #pragma unroll
            for (int j = 0; j < 4; j++) sacc[i][j] = 0.f;
        {
            int br = wn * 32 + (lane & 7) + (lane >> 4) * 8;
            int bb0 = ((lane >> 3) & 1) * 16;
            #pragma unroll
            for (int ks = 0; ks < 8; ks++) {
                uint32_t qfh[4], qfl[4];
                uint32_t qoff = sw256(qar, ks * 32 + qab);
                ldsm4(qfh, sb + AQ_OFF + qoff);
                ldsm4(qfl, sb + AQ_OFF + 32768u + qoff);
                #pragma unroll
                for (int np = 0; np < 2; np++) {
                    uint32_t bh[4], bl[4];
                    uint32_t off = sw256(br + np * 16, ks * 32 + bb0);
                    ldsm4(bh, kbuf + off);
                    ldsm4(bl, kbuf + 16384u + off);
                    mma16816(sacc[np * 2],     qfh, bh + 0);
                    mma16816(sacc[np * 2],     qfh, bl + 0);
                    mma16816(sacc[np * 2],     qfl, bh + 0);
                    mma16816(sacc[np * 2 + 1], qfh, bh + 2);
                    mma16816(sacc[np * 2 + 1], qfh, bl + 2);
                    mma16816(sacc[np * 2 + 1], qfl, bh + 2);
                }
            }
        }

        // ---- online softmax ----
        float mx1 = -1e30f, mx2 = -1e30f;
        #pragma unroll
        for (int nt = 0; nt < 4; nt++) {
            mx1 = fmaxf(mx1, fmaxf(sacc[nt][0], sacc[nt][1]));
            mx2 = fmaxf(mx2, fmaxf(sacc[nt][2], sacc[nt][3]));
        }
        mx1 = fmaxf(mx1, __shfl_xor_sync(0xffffffffu, mx1, 1));
        mx1 = fmaxf(mx1, __shfl_xor_sync(0xffffffffu, mx1, 2));
        mx2 = fmaxf(mx2, __shfl_xor_sync(0xffffffffu, mx2, 1));
        mx2 = fmaxf(mx2, __shfl_xor_sync(0xffffffffu, mx2, 2));
        if ((lane & 3) == 0) {
            redm[wn * 128 + row1] = mx1;
            redm[wn * 128 + row2] = mx2;
        }
        __syncthreads();                                  // BAR-A

        float mn1 = fmaxf(m[0], fmaxf(redm[row1], redm[128 + row1]));
        float mn2 = fmaxf(m[1], fmaxf(redm[row2], redm[128 + row2]));
        float al1 = __expf(m[0] - mn1), al2 = __expf(m[1] - mn2);
        float p[4][4], s1 = 0.f, s2 = 0.f;
        #pragma unroll
        for (int nt = 0; nt < 4; nt++) {
            p[nt][0] = __expf(sacc[nt][0] - mn1);
            p[nt][1] = __expf(sacc[nt][1] - mn1);
            p[nt][2] = __expf(sacc[nt][2] - mn2);
            p[nt][3] = __expf(sacc[nt][3] - mn2);
            s1 += p[nt][0] + p[nt][1];
            s2 += p[nt][2] + p[nt][3];
        }
        s1 += __shfl_xor_sync(0xffffffffu, s1, 1);
        s1 += __shfl_xor_sync(0xffffffffu, s1, 2);
        s2 += __shfl_xor_sync(0xffffffffu, s2, 1);
        s2 += __shfl_xor_sync(0xffffffffu, s2, 2);
        if ((lane & 3) == 0) {
            reds[wn * 128 + row1] = s1;
            reds[wn * 128 + row2] = s2;
        }
        {
            int cb = wn * 64 + (lane & 3) * 4;
            #pragma unroll
            for (int nt = 0; nt < 4; nt++) {
                float h0 = p[nt][0], h1 = p[nt][1], h2 = p[nt][2], h3 = p[nt][3];
                uint32_t ph01 = packbf(h0, h1), ph23 = packbf(h2, h3);
                __nv_bfloat162 b01 = *(__nv_bfloat162*)&ph01;
                __nv_bfloat162 b23 = *(__nv_bfloat162*)&ph23;
                uint32_t pl01 = packbf(h0 - __bfloat162float(b01.x), h1 - __bfloat162float(b01.y));
                uint32_t pl23 = packbf(h2 - __bfloat162float(b23.x), h3 - __bfloat162float(b23.y));
                uint32_t o1 = sw128(row1, cb + nt * 16);
                uint32_t o2 = sw128(row2, cb + nt * 16);
                *(uint32_t*)(sm + APH_OFF + o1) = ph01;
                *(uint32_t*)(sm + APH_OFF + o2) = ph23;
                *(uint32_t*)(sm + APL_OFF + o1) = pl01;
                *(uint32_t*)(sm + APL_OFF + o2) = pl23;
            }
        }
        __syncthreads();                                  // BAR-B
        {
            float tot1 = reds[row1] + reds[128 + row1];
            float tot2 = reds[row2] + reds[128 + row2];
            l[0] = l[0] * al1 + tot1;
            l[1] = l[1] * al2 + tot2;
            m[0] = mn1; m[1] = mn2;
            #pragma unroll
            for (int nt = 0; nt < 8; nt++) {
                oacc[nt][0] *= al1; oacc[nt][1] *= al1;
                oacc[nt][2] *= al2; oacc[nt][3] *= al2;
            }
        }

        // ---- PV ----
        {
            int par = wm * 16 + (lane & 7) + ((lane >> 3) & 1) * 8;
            int pab = (lane >> 4) * 16;
            int vr0 = (lane & 7) + ((lane >> 3) & 1) * 8;
            int vb0 = wn * 128 + (lane >> 4) * 16;
            #pragma unroll
            for (int ks = 0; ks < 4; ks++) {
                uint32_t pfh[4], pfl[4];
                ldsm4(pfh, sb + APH_OFF + sw128(par, ks * 32 + pab));
                ldsm4(pfl, sb + APL_OFF + sw128(par, ks * 32 + pab));
                #pragma unroll
                for (int np = 0; np < 4; np++) {
                    uint32_t wh[4], wl[4];
                    uint32_t off = sw256(ks * 16 + vr0, vb0 + np * 32);
                    ldsm4t(wh, vbuf + off);
                    ldsm4t(wl, vbuf + 16384u + off);
                    mma16816(oacc[np * 2],     pfh, wh + 0);
                    mma16816(oacc[np * 2],     pfh, wl + 0);
                    mma16816(oacc[np * 2],     pfl, wh + 0);
                    mma16816(oacc[np * 2 + 1], pfh, wh + 2);
                    mma16816(oacc[np * 2 + 1], pfh, wl + 2);
                    mma16816(oacc[np * 2 + 1], pfl, wh + 2);
                }
            }
        }
        __syncthreads();                                  // BAR-C (P + KV buf reuse)
    }

    // ---- epilogue ----
    {
        float inv1 = 1.f / l[0], inv2 = 1.f / l[1];
        int rg1 = qt * 128 + row1, rg2 = qt * 128 + row2;
        size_t b1 = ((size_t)(b * SEQ + rg1) * NH + h) * HD;
        size_t b2 = ((size_t)(b * SEQ + rg2) * NH + h) * HD;
        #pragma unroll
        for (int nt = 0; nt < 8; nt++) {
            int c0 = wn * 64 + nt * 8 + (lane & 3) * 2;
            float f0 = oacc[nt][0] * inv1, f1 = oacc[nt][1] * inv1;
            float f2 = oacc[nt][2] * inv2, f3 = oacc[nt][3] * inv2;
            uint32_t h01 = packbf(f0, f1), h23 = packbf(f2, f3);
            __nv_bfloat162 bb01 = *(__nv_bfloat162*)&h01;
            __nv_bfloat162 bb23 = *(__nv_bfloat162*)&h23;
            uint32_t l01 = packbf(f0 - __bfloat162float(bb01.x), f1 - __bfloat162float(bb01.y));
            uint32_t l23 = packbf(f2 - __bfloat162float(bb23.x), f3 - __bfloat162float(bb23.y));
            *(uint32_t*)(outh + b1 + c0) = h01;
            *(uint32_t*)(outh + b2 + c0) = h23;
            *(uint32_t*)(outl + b1 + c0) = l01;
            *(uint32_t*)(outl + b2 + c0) = l23;
        }
    }
#undef LOAD_KV
}

// ============================================================
// launch  (attn_mma at launch index 3 for the ncu capture slot)
// ============================================================
extern "C" void kernel_launch(void* const* d_in, const int* in_sizes, int n_in,
                              void* d_out, int out_size)
{
    const float* x  = (const float*)d_in[0];
    const float* wq = (const float*)d_in[1];
    const float* wk = (const float*)d_in[2];
    const float* wv = (const float*)d_in[3];
    const float* wo = (const float*)d_in[4];
    const float* fcos = (const float*)d_in[7];
    const float* fsin = (const float*)d_in[8];
    float* out = (float*)d_out;

    float* gqkv;
    __nv_bfloat16 *xh, *xl, *wqkvTh, *wqkvTl, *woTh, *woTl;
    __nv_bfloat16 *aoh, *aol, *pqh, *pql, *pkh, *pkl, *pvh, *pvl;
    cudaGetSymbolAddress((void**)&gqkv, g_qkv);
    cudaGetSymbolAddress((void**)&xh, g_xh);         cudaGetSymbolAddress((void**)&xl, g_xl);
    cudaGetSymbolAddress((void**)&wqkvTh, g_wqkvTh); cudaGetSymbolAddress((void**)&wqkvTl, g_wqkvTl);
    cudaGetSymbolAddress((void**)&woTh, g_woTh);     cudaGetSymbolAddress((void**)&woTl, g_woTl);
    cudaGetSymbolAddress((void**)&aoh, g_aoh);       cudaGetSymbolAddress((void**)&aol, g_aol);
    cudaGetSymbolAddress((void**)&pqh, g_qh);        cudaGetSymbolAddress((void**)&pql, g_ql);
    cudaGetSymbolAddress((void**)&pkh, g_kh);        cudaGetSymbolAddress((void**)&pkl, g_kl);
    cudaGetSymbolAddress((void**)&pvh, g_vh);        cudaGetSymbolAddress((void**)&pvl, g_vl);

    cudaFuncSetAttribute(gemm_mma, cudaFuncAttributeMaxDynamicSharedMemorySize, GEMM_SMEM);
    cudaFuncSetAttribute(attn_mma, cudaFuncAttributeMaxDynamicSharedMemorySize, ATT_SMEM);

    // 0: prep (x split + all weight transposes)
    prep_kernel<<<PREP_TOTAL, 256>>>(x, wq, wk, wv, wo, xh, xl, wqkvTh, wqkvTl, woTh, woTl);
    // 1: fused qkv projection
    gemm_mma<<<dim3(NQKV / BN, MTOT / BM), 512, GEMM_SMEM>>>(xh, xl, wqkvTh, wqkvTl,
                                                             gqkv, MTOT, NQKV, DIM);
    // 2: rope + split + relayout
    {
        int total = BATCH * SEQ * (NH + 2 * NKV) * (HD / 2);
        rope_split<<<(total + 255) / 256, 256>>>(gqkv, fcos, fsin,
                                                 pqh, pql, pkh, pkl, pvh, pvl);
    }
    // 3: attention  <-- ncu capture slot
    {
        dim3 grid(SEQ / 128, NH, BATCH);
        attn_mma<<<grid, 512, ATT_SMEM>>>(pqh, pql, pkh, pkl, pvh, pvl, aoh, aol);
    }
    // 4: output projection
    gemm_mma<<<dim3(DIM / BN, MTOT / BM), 512, GEMM_SMEM>>>(aoh, aol, woTh, woTl, out, MTOT, DIM, NQ);
}